// round 1
// baseline (speedup 1.0000x reference)
#include <cuda_runtime.h>

#define EMBED 1024
#define HEADS 16
#define HDIM 64
#define TT 512
#define SS 512
#define BATCH 8
#define NHB (BATCH*HEADS)   /* 128 */
#define MROWS (TT*BATCH)    /* 4096 */

// ---------------- scratch (static device globals; no allocation allowed) ----
__device__ float g_qp  [NHB*TT*HDIM];   // [n][t][d]  (scaled)
__device__ float g_kpT [NHB*HDIM*SS];   // [n][d][s]  (transposed for energy GEMM)
__device__ float g_vp  [NHB*SS*HDIM];   // [n][s][d]
__device__ float g_p   [NHB*TT*SS];     // p_choose
__device__ float g_pc  [NHB*TT*SS];     // p * cumprod_1mp
__device__ float g_cl  [NHB*TT*SS];     // clamp(cumprod_1mp, eps, 1)
__device__ float g_alpha[NHB*TT*SS];    // alpha (with mass-preserved last col)
__device__ float g_attn[MROWS*EMBED];   // merged [t*B+b][h*64+d]

// ============================================================================
// Projection GEMM: C = A[4096x1024] @ W[1024x1024]; scatter-store into split
// head layout. which: 0 -> g_qp [n][t][d], 1 -> g_kpT [n][d][s], 2 -> g_vp.
// BM=BN=128, BK=8, 256 threads, 8x8 per thread.
// ============================================================================
__global__ __launch_bounds__(256) void gemm_proj_kernel(
    const float* __restrict__ A, const float* __restrict__ W,
    float scale, int which)
{
    __shared__ float As[8][128];
    __shared__ float Bs[8][128];
    const int tid = threadIdx.x;
    const int bm = blockIdx.y * 128;
    const int bn = blockIdx.x * 128;
    const int aRow = tid >> 1, aCol = (tid & 1) * 4;
    const int bRow = tid >> 5, bCol = (tid & 31) * 4;
    const int ty = tid >> 4, tx = tid & 15;

    float acc[8][8];
#pragma unroll
    for (int i = 0; i < 8; i++)
#pragma unroll
        for (int j = 0; j < 8; j++) acc[i][j] = 0.f;

    for (int k0 = 0; k0 < 1024; k0 += 8) {
        float4 av = *(const float4*)&A[(bm + aRow) * 1024 + k0 + aCol];
        As[aCol + 0][aRow] = av.x;
        As[aCol + 1][aRow] = av.y;
        As[aCol + 2][aRow] = av.z;
        As[aCol + 3][aRow] = av.w;
        *(float4*)&Bs[bRow][bCol] =
            *(const float4*)&W[(k0 + bRow) * 1024 + bn + bCol];
        __syncthreads();
#pragma unroll
        for (int kk = 0; kk < 8; kk++) {
            float a[8], b[8];
            *(float4*)&a[0] = *(const float4*)&As[kk][ty * 8];
            *(float4*)&a[4] = *(const float4*)&As[kk][ty * 8 + 4];
            *(float4*)&b[0] = *(const float4*)&Bs[kk][tx * 8];
            *(float4*)&b[4] = *(const float4*)&Bs[kk][tx * 8 + 4];
#pragma unroll
            for (int i = 0; i < 8; i++)
#pragma unroll
                for (int j = 0; j < 8; j++)
                    acc[i][j] = fmaf(a[i], b[j], acc[i][j]);
        }
        __syncthreads();
    }

    float* dst = (which == 0) ? g_qp : (which == 1) ? g_kpT : g_vp;
#pragma unroll
    for (int i = 0; i < 8; i++) {
        int r = bm + ty * 8 + i;
        int t = r >> 3;        // time/seq index
        int b = r & 7;         // batch
#pragma unroll
        for (int j = 0; j < 8; j++) {
            int f = bn + tx * 8 + j;
            int h = f >> 6, d = f & 63;
            int n = b * 16 + h;
            float v = acc[i][j] * scale;
            if (which == 1) dst[(n * 64 + d) * 512 + t] = v;
            else            dst[(n * 512 + t) * 64 + d] = v;
        }
    }
}

// ============================================================================
// Energy + sigmoid: p[n][t][s] = sigmoid(qp_n[t,:] . kp_n[s,:] + bias)
// Batched GEMM: A = g_qp (lda=64), B = g_kpT (ldb=512), K=64.
// grid (4,4,128), BM=BN=128, BK=8, 256 threads.
// ============================================================================
__global__ __launch_bounds__(256) void energy_kernel(const float* __restrict__ ebias)
{
    __shared__ float As[8][128];
    __shared__ float Bs[8][128];
    const int n = blockIdx.z;
    const int t0 = blockIdx.y * 128;
    const int s0 = blockIdx.x * 128;
    const float* A = g_qp  + n * 512 * 64;
    const float* B = g_kpT + n * 64 * 512;

    const int tid = threadIdx.x;
    const int aRow = tid >> 1, aCol = (tid & 1) * 4;
    const int bRow = tid >> 5, bCol = (tid & 31) * 4;
    const int ty = tid >> 4, tx = tid & 15;

    float acc[8][8];
#pragma unroll
    for (int i = 0; i < 8; i++)
#pragma unroll
        for (int j = 0; j < 8; j++) acc[i][j] = 0.f;

    for (int k0 = 0; k0 < 64; k0 += 8) {
        float4 av = *(const float4*)&A[(t0 + aRow) * 64 + k0 + aCol];
        As[aCol + 0][aRow] = av.x;
        As[aCol + 1][aRow] = av.y;
        As[aCol + 2][aRow] = av.z;
        As[aCol + 3][aRow] = av.w;
        *(float4*)&Bs[bRow][bCol] =
            *(const float4*)&B[(k0 + bRow) * 512 + s0 + bCol];
        __syncthreads();
#pragma unroll
        for (int kk = 0; kk < 8; kk++) {
            float a[8], b[8];
            *(float4*)&a[0] = *(const float4*)&As[kk][ty * 8];
            *(float4*)&a[4] = *(const float4*)&As[kk][ty * 8 + 4];
            *(float4*)&b[0] = *(const float4*)&Bs[kk][tx * 8];
            *(float4*)&b[4] = *(const float4*)&Bs[kk][tx * 8 + 4];
#pragma unroll
            for (int i = 0; i < 8; i++)
#pragma unroll
                for (int j = 0; j < 8; j++)
                    acc[i][j] = fmaf(a[i], b[j], acc[i][j]);
        }
        __syncthreads();
    }

    const float eb = ebias[0];
#pragma unroll
    for (int i = 0; i < 8; i++) {
        int t = t0 + ty * 8 + i;
#pragma unroll
        for (int j = 0; j < 8; j++) {
            int s = s0 + tx * 8 + j;
            float e = acc[i][j] + eb;
            float p = 1.f / (1.f + __expf(-e));
            g_p[(n * 512 + t) * 512 + s] = p;
        }
    }
}

// ============================================================================
// Per-row exclusive cumprod of (1-p) along S via block product-scan.
// grid (512 /*t*/, 128 /*n*/), 512 threads (one per s).
// Outputs: pc = p * cumprod ; cl = clamp(cumprod, 1e-6, 1)
// ============================================================================
__global__ __launch_bounds__(512) void cumprod_kernel()
{
    const int s = threadIdx.x;
    const int t = blockIdx.x;
    const int n = blockIdx.y;
    const int idx = (n * 512 + t) * 512 + s;
    const int lane = s & 31, wid = s >> 5;

    __shared__ float wprod[16], wpre[16], incl_sh[512];

    float p = g_p[idx];
    float v = 1.f - p;
#pragma unroll
    for (int o = 1; o < 32; o <<= 1) {
        float u = __shfl_up_sync(0xffffffffu, v, o);
        if (lane >= o) v *= u;
    }
    if (lane == 31) wprod[wid] = v;
    __syncthreads();
    if (wid == 0) {
        float w = (lane < 16) ? wprod[lane] : 1.f;
#pragma unroll
        for (int o = 1; o < 16; o <<= 1) {
            float u = __shfl_up_sync(0xffffffffu, w, o);
            if (lane >= o) w *= u;
        }
        if (lane < 16) wpre[lane] = w;
    }
    __syncthreads();
    float incl = v * (wid > 0 ? wpre[wid - 1] : 1.f);
    incl_sh[s] = incl;
    __syncthreads();
    float cp = (s == 0) ? 1.f : incl_sh[s - 1];   // exclusive product
    float clv = fminf(fmaxf(cp, 1e-6f), 1.f);
    g_pc[idx] = p * cp;
    g_cl[idx] = clv;
}

// ============================================================================
// Sequential recurrence over t (the true serial dependency).
// One block per n (128 blocks), 512 threads (one per s).
// alpha_t = clip(pc_t * cumsum_s(alpha_{t-1}/cl_t), 0, 1)
// Stored alpha has last column replaced by 1 - clip(sum(alpha[:-1]),0,1),
// but the RAW alpha is carried to t+1 (matches jax.lax.scan semantics).
// ============================================================================
__global__ __launch_bounds__(512) void recurrence_kernel()
{
    const int s = threadIdx.x;
    const int n = blockIdx.x;
    const int lane = s & 31, wid = s >> 5;
    const int base = n * 512 * 512 + s;

    __shared__ float wsh[16], wpre[16];

    float aprev = (s == 0) ? 1.f : 0.f;
    float pcv = g_pc[base];
    float clv = g_cl[base];

    for (int t = 0; t < 512; t++) {
        // prefetch next row
        float pcn = 0.f, cln = 1.f;
        if (t < 511) {
            pcn = g_pc[base + (t + 1) * 512];
            cln = g_cl[base + (t + 1) * 512];
        }

        float v = aprev / clv;
        // block-wide inclusive sum scan
#pragma unroll
        for (int o = 1; o < 32; o <<= 1) {
            float u = __shfl_up_sync(0xffffffffu, v, o);
            if (lane >= o) v += u;
        }
        if (lane == 31) wsh[wid] = v;
        __syncthreads();
        if (wid == 0) {
            float w = (lane < 16) ? wsh[lane] : 0.f;
#pragma unroll
            for (int o = 1; o < 16; o <<= 1) {
                float u = __shfl_up_sync(0xffffffffu, w, o);
                if (lane >= o) w += u;
            }
            if (lane < 16) wpre[lane] = w;
        }
        __syncthreads();
        float incl = v + (wid > 0 ? wpre[wid - 1] : 0.f);
        float araw = fminf(fmaxf(pcv * incl, 0.f), 1.f);

        // sum over s < 511 for mass preservation on last column
        float yv = (s < 511) ? araw : 0.f;
#pragma unroll
        for (int o = 16; o > 0; o >>= 1)
            yv += __shfl_xor_sync(0xffffffffu, yv, o);
        if (lane == 0) wsh[wid] = yv;
        __syncthreads();

        if (s == 511) {
            float total = 0.f;
#pragma unroll
            for (int i = 0; i < 16; i++) total += wsh[i];
            float clipped = fminf(fmaxf(total, 0.f), 1.f);
            g_alpha[base + t * 512] = 1.f - clipped;
        } else {
            g_alpha[base + t * 512] = araw;
        }
        __syncthreads();   // protect wsh reuse next iteration

        aprev = araw;      // raw alpha carries (mass fix is output-only)
        pcv = pcn;
        clv = cln;
    }
}

// ============================================================================
// attn = alpha @ vp  (batched, per n: [512x512]@[512x64]) -> merged layout.
// grid (1,4,128), BM=128, BN=64, BK=8, 256 threads, 8x4 per thread.
// ============================================================================
__global__ __launch_bounds__(256) void attnv_kernel()
{
    __shared__ float As[8][128];
    __shared__ float Bs[8][64];
    const int n = blockIdx.z;
    const int t0 = blockIdx.y * 128;
    const float* A = g_alpha + n * 512 * 512;
    const float* B = g_vp    + n * 512 * 64;

    const int tid = threadIdx.x;
    const int aRow = tid >> 1, aCol = (tid & 1) * 4;
    const int bRow = tid >> 5, bCol = (tid & 31) * 2;
    const int ty = tid >> 4, tx = tid & 15;

    float acc[8][4];
#pragma unroll
    for (int i = 0; i < 8; i++)
#pragma unroll
        for (int j = 0; j < 4; j++) acc[i][j] = 0.f;

    for (int k0 = 0; k0 < 512; k0 += 8) {
        float4 av = *(const float4*)&A[(t0 + aRow) * 512 + k0 + aCol];
        As[aCol + 0][aRow] = av.x;
        As[aCol + 1][aRow] = av.y;
        As[aCol + 2][aRow] = av.z;
        As[aCol + 3][aRow] = av.w;
        *(float2*)&Bs[bRow][bCol] =
            *(const float2*)&B[(k0 + bRow) * 64 + bCol];
        __syncthreads();
#pragma unroll
        for (int kk = 0; kk < 8; kk++) {
            float a[8], b[4];
            *(float4*)&a[0] = *(const float4*)&As[kk][ty * 8];
            *(float4*)&a[4] = *(const float4*)&As[kk][ty * 8 + 4];
            *(float4*)&b[0] = *(const float4*)&Bs[kk][tx * 4];
#pragma unroll
            for (int i = 0; i < 8; i++)
#pragma unroll
                for (int j = 0; j < 4; j++)
                    acc[i][j] = fmaf(a[i], b[j], acc[i][j]);
        }
        __syncthreads();
    }

    const int b = n >> 4, h = n & 15;
#pragma unroll
    for (int i = 0; i < 8; i++) {
        int t = t0 + ty * 8 + i;
#pragma unroll
        for (int j = 0; j < 4; j++) {
            int d = tx * 4 + j;
            g_attn[(t * 8 + b) * 1024 + h * 64 + d] = acc[i][j];
        }
    }
}

// ============================================================================
// Output projection: out = g_attn[4096x1024] @ Wo + bo
// ============================================================================
__global__ __launch_bounds__(256) void gemm_out_kernel(
    const float* __restrict__ W, const float* __restrict__ bias,
    float* __restrict__ out)
{
    __shared__ float As[8][128];
    __shared__ float Bs[8][128];
    const int tid = threadIdx.x;
    const int bm = blockIdx.y * 128;
    const int bn = blockIdx.x * 128;
    const int aRow = tid >> 1, aCol = (tid & 1) * 4;
    const int bRow = tid >> 5, bCol = (tid & 31) * 4;
    const int ty = tid >> 4, tx = tid & 15;

    float acc[8][8];
#pragma unroll
    for (int i = 0; i < 8; i++)
#pragma unroll
        for (int j = 0; j < 8; j++) acc[i][j] = 0.f;

    for (int k0 = 0; k0 < 1024; k0 += 8) {
        float4 av = *(const float4*)&g_attn[(bm + aRow) * 1024 + k0 + aCol];
        As[aCol + 0][aRow] = av.x;
        As[aCol + 1][aRow] = av.y;
        As[aCol + 2][aRow] = av.z;
        As[aCol + 3][aRow] = av.w;
        *(float4*)&Bs[bRow][bCol] =
            *(const float4*)&W[(k0 + bRow) * 1024 + bn + bCol];
        __syncthreads();
#pragma unroll
        for (int kk = 0; kk < 8; kk++) {
            float a[8], b[8];
            *(float4*)&a[0] = *(const float4*)&As[kk][ty * 8];
            *(float4*)&a[4] = *(const float4*)&As[kk][ty * 8 + 4];
            *(float4*)&b[0] = *(const float4*)&Bs[kk][tx * 8];
            *(float4*)&b[4] = *(const float4*)&Bs[kk][tx * 8 + 4];
#pragma unroll
            for (int i = 0; i < 8; i++)
#pragma unroll
                for (int j = 0; j < 8; j++)
                    acc[i][j] = fmaf(a[i], b[j], acc[i][j]);
        }
        __syncthreads();
    }

#pragma unroll
    for (int i = 0; i < 8; i++) {
        int r = bm + ty * 8 + i;
#pragma unroll
        for (int j = 0; j < 8; j++) {
            int f = bn + tx * 8 + j;
            out[r * 1024 + f] = acc[i][j] + bias[f];
        }
    }
}

// ============================================================================
extern "C" void kernel_launch(void* const* d_in, const int* in_sizes, int n_in,
                              void* d_out, int out_size)
{
    const float* q  = (const float*)d_in[0];
    const float* k  = (const float*)d_in[1];
    const float* v  = (const float*)d_in[2];
    const float* Wq = (const float*)d_in[3];
    const float* Wk = (const float*)d_in[4];
    const float* Wv = (const float*)d_in[5];
    const float* Wo = (const float*)d_in[6];
    const float* bo = (const float*)d_in[7];
    const float* eb = (const float*)d_in[8];
    float* out = (float*)d_out;

    dim3 gProj(8, 32, 1);
    gemm_proj_kernel<<<gProj, 256>>>(q, Wq, 0.125f, 0);  // scaling = D^-0.5
    gemm_proj_kernel<<<gProj, 256>>>(k, Wk, 1.0f, 1);    // transposed kpT
    gemm_proj_kernel<<<gProj, 256>>>(v, Wv, 1.0f, 2);

    energy_kernel<<<dim3(4, 4, 128), 256>>>(eb);
    cumprod_kernel<<<dim3(512, 128), 512>>>();
    recurrence_kernel<<<128, 512>>>();
    attnv_kernel<<<dim3(1, 4, 128), 256>>>();
    gemm_out_kernel<<<gProj, 256>>>(Wo, bo, out);
}

// round 3
// speedup vs baseline: 1.3232x; 1.3232x over previous
#include <cuda_runtime.h>
#include <cuda_bf16.h>
#include <cstdint>

typedef __nv_bfloat16 bf16;

#define EMBED 1024
#define TT 512
#define SS 512
#define BATCH 8
#define NHB 128
#define MROWS 4096

// ---------------- scratch (static device globals; no allocation allowed) ----
__device__ bf16 g_q_h[MROWS*EMBED],  g_q_l[MROWS*EMBED];
__device__ bf16 g_k_h[MROWS*EMBED],  g_k_l[MROWS*EMBED];
__device__ bf16 g_v_h[MROWS*EMBED],  g_v_l[MROWS*EMBED];
__device__ bf16 g_Wq_h[EMBED*EMBED], g_Wq_l[EMBED*EMBED];
__device__ bf16 g_Wk_h[EMBED*EMBED], g_Wk_l[EMBED*EMBED];
__device__ bf16 g_Wv_h[EMBED*EMBED], g_Wv_l[EMBED*EMBED];
__device__ bf16 g_Wo_h[EMBED*EMBED], g_Wo_l[EMBED*EMBED];
__device__ bf16 g_qp_h [NHB*TT*64],  g_qp_l [NHB*TT*64];   // [n][t][d]
__device__ bf16 g_kpT_h[NHB*64*SS],  g_kpT_l[NHB*64*SS];   // [n][d][s]
__device__ bf16 g_vp_h [NHB*SS*64],  g_vp_l [NHB*SS*64];   // [n][s][d]
__device__ float g_p [NHB*TT*SS];
__device__ float g_pc[NHB*TT*SS];
__device__ float g_cl[NHB*TT*SS];
__device__ bf16 g_al_h[NHB*TT*SS],   g_al_l[NHB*TT*SS];    // [n][t][s]
__device__ bf16 g_at_h[MROWS*EMBED], g_at_l[MROWS*EMBED];  // merged [t*8+b][h*64+d]

// ============================================================================
// PTX helpers
// ============================================================================
__device__ __forceinline__ uint32_t smem_u32(const void* p) {
    uint32_t a;
    asm("{ .reg .u64 t; cvta.to.shared.u64 t, %1; cvt.u32.u64 %0, t; }"
        : "=r"(a) : "l"(p));
    return a;
}
__device__ __forceinline__ void ldmA(uint32_t r[4], uint32_t addr) {
    asm volatile("ldmatrix.sync.aligned.m8n8.x4.shared.b16 {%0,%1,%2,%3},[%4];"
        : "=r"(r[0]), "=r"(r[1]), "=r"(r[2]), "=r"(r[3]) : "r"(addr));
}
__device__ __forceinline__ void ldmBT(uint32_t r[4], uint32_t addr) {
    asm volatile("ldmatrix.sync.aligned.m8n8.x4.trans.shared.b16 {%0,%1,%2,%3},[%4];"
        : "=r"(r[0]), "=r"(r[1]), "=r"(r[2]), "=r"(r[3]) : "r"(addr));
}
__device__ __forceinline__ void mma16816(float c[4], const uint32_t a[4],
                                         uint32_t b0, uint32_t b1) {
    asm volatile(
        "mma.sync.aligned.m16n8k16.row.col.f32.bf16.bf16.f32 "
        "{%0,%1,%2,%3},{%4,%5,%6,%7},{%8,%9},{%0,%1,%2,%3};"
        : "+f"(c[0]), "+f"(c[1]), "+f"(c[2]), "+f"(c[3])
        : "r"(a[0]), "r"(a[1]), "r"(a[2]), "r"(a[3]), "r"(b0), "r"(b1));
}

// ============================================================================
// bf16x3 GEMM core. Block = 128 x BN, 256 threads (8 warps, 4x2).
// acc += Ah*Bh + Ah*Bl + Al*Bh
// ============================================================================
template<int BN>
__device__ __forceinline__ void gemm_core(
    const bf16* __restrict__ Ah, const bf16* __restrict__ Al, int lda,
    const bf16* __restrict__ Bh, const bf16* __restrict__ Bl, int ldb,
    int K, float acc[2][BN/16][4])
{
    constexpr int NT = BN / 16;
    constexpr int BSTR = BN + 40;   // row stride = 20 banks mod 32 -> LDSM conflict-free
    __shared__ bf16 sA[2 * 128 * 40];
    __shared__ bf16 sB[2 * 32 * BSTR];
    const int tid = threadIdx.x;
    const int lane = tid & 31, wid = tid >> 5;
    const int wm = wid & 3, wn = wid >> 2;

    for (int k0 = 0; k0 < K; k0 += 32) {
#pragma unroll
        for (int i = 0; i < 2; i++) {
            int id = tid + i * 256;
            int r = id >> 2, cc = (id & 3) * 8;
            *(uint4*)(sA + r * 40 + cc) = *(const uint4*)(Ah + r * lda + k0 + cc);
            *(uint4*)(sA + 128 * 40 + r * 40 + cc) = *(const uint4*)(Al + r * lda + k0 + cc);
        }
        constexpr int BCH = (BN / 8) * 32 / 256;
#pragma unroll
        for (int i = 0; i < BCH; i++) {
            int id = tid + i * 256;
            int r = id / (BN / 8), cc = (id % (BN / 8)) * 8;
            *(uint4*)(sB + r * BSTR + cc) = *(const uint4*)(Bh + (k0 + r) * ldb + cc);
            *(uint4*)(sB + 32 * BSTR + r * BSTR + cc) = *(const uint4*)(Bl + (k0 + r) * ldb + cc);
        }
        __syncthreads();
#pragma unroll
        for (int pass = 0; pass < 3; pass++) {
            const bf16* pA = sA + (pass == 2 ? 128 * 40 : 0);
            const bf16* pB = sB + (pass == 1 ? 32 * BSTR : 0);
#pragma unroll
            for (int kk = 0; kk < 32; kk += 16) {
                uint32_t bfr[NT][2];
#pragma unroll
                for (int np = 0; np < NT / 2; np++) {
                    int row = kk + (lane & 15);
                    int col = wn * (NT * 8) + np * 16 + ((lane >> 4) << 3);
                    uint32_t rr[4];
                    ldmBT(rr, smem_u32(pB + row * BSTR + col));
                    bfr[2 * np][0] = rr[0]; bfr[2 * np][1] = rr[1];
                    bfr[2 * np + 1][0] = rr[2]; bfr[2 * np + 1][1] = rr[3];
                }
#pragma unroll
                for (int mt = 0; mt < 2; mt++) {
                    int row = wm * 32 + mt * 16 + (lane & 15);
                    int col = kk + ((lane >> 4) << 3);
                    uint32_t a[4];
                    ldmA(a, smem_u32(pA + row * 40 + col));
#pragma unroll
                    for (int nt = 0; nt < NT; nt++)
                        mma16816(acc[mt][nt], a, bfr[nt][0], bfr[nt][1]);
                }
            }
        }
        __syncthreads();
    }
}

#define EPI_ROW(mt, r)     (wm * 32 + (mt) * 16 + (lane >> 2) + (((r) >> 1) << 3))
#define EPI_COL(nt, r, NT) (wn * ((NT) * 8) + (nt) * 8 + ((lane & 3) << 1) + ((r) & 1))

// ============================================================================
// split: fp32 -> (bf16 hi, bf16 lo). Destination selected INSIDE device code.
// which: 0..6 = q,k,v,Wq,Wk,Wv,Wo
// ============================================================================
__global__ void split_kernel(const float* __restrict__ x, int which, int n)
{
    bf16 *h, *l;
    switch (which) {
        case 0: h = g_q_h;  l = g_q_l;  break;
        case 1: h = g_k_h;  l = g_k_l;  break;
        case 2: h = g_v_h;  l = g_v_l;  break;
        case 3: h = g_Wq_h; l = g_Wq_l; break;
        case 4: h = g_Wk_h; l = g_Wk_l; break;
        case 5: h = g_Wv_h; l = g_Wv_l; break;
        default: h = g_Wo_h; l = g_Wo_l; break;
    }
    int i = blockIdx.x * blockDim.x + threadIdx.x;
    if (i < n) {
        float v = x[i];
        bf16 hv = __float2bfloat16(v);
        h[i] = hv;
        l[i] = __float2bfloat16(v - __bfloat162float(hv));
    }
}

// ============================================================================
// Projection GEMM: [4096x1024] @ [1024x1024], scatter to head-split hi/lo.
// which: 0 -> qp (scaled), 1 -> kpT, 2 -> vp. All globals resolved in device code.
// ============================================================================
__global__ __launch_bounds__(256) void proj_mma_kernel(float scale, int which)
{
    const bf16 *Ah, *Al, *Wh, *Wl;
    if (which == 0)      { Ah = g_q_h; Al = g_q_l; Wh = g_Wq_h; Wl = g_Wq_l; }
    else if (which == 1) { Ah = g_k_h; Al = g_k_l; Wh = g_Wk_h; Wl = g_Wk_l; }
    else                 { Ah = g_v_h; Al = g_v_l; Wh = g_Wv_h; Wl = g_Wv_l; }

    const int bm = blockIdx.y * 128, bn = blockIdx.x * 128;
    float acc[2][8][4];
#pragma unroll
    for (int i = 0; i < 2; i++)
#pragma unroll
        for (int j = 0; j < 8; j++)
#pragma unroll
            for (int r = 0; r < 4; r++) acc[i][j][r] = 0.f;

    gemm_core<128>(Ah + bm * 1024, Al + bm * 1024, 1024,
                   Wh + bn, Wl + bn, 1024, 1024, acc);

    const int lane = threadIdx.x & 31, wid = threadIdx.x >> 5;
    const int wm = wid & 3, wn = wid >> 2;
    bf16 *dh, *dl;
    if (which == 0)      { dh = g_qp_h;  dl = g_qp_l;  }
    else if (which == 1) { dh = g_kpT_h; dl = g_kpT_l; }
    else                 { dh = g_vp_h;  dl = g_vp_l;  }

#pragma unroll
    for (int mt = 0; mt < 2; mt++)
#pragma unroll
        for (int nt = 0; nt < 8; nt++)
#pragma unroll
            for (int r = 0; r < 4; r++) {
                int row = bm + EPI_ROW(mt, r);
                int col = bn + EPI_COL(nt, r, 8);
                int t = row >> 3, b = row & 7;
                int h = col >> 6, d = col & 63;
                int n = b * 16 + h;
                float v = acc[mt][nt][r] * scale;
                int idx = (which == 1) ? (n * 64 + d) * 512 + t
                                       : (n * 512 + t) * 64 + d;
                bf16 hv = __float2bfloat16(v);
                dh[idx] = hv;
                dl[idx] = __float2bfloat16(v - __bfloat162float(hv));
            }
}

// ============================================================================
// Energy + sigmoid
// ============================================================================
__global__ __launch_bounds__(256) void energy_mma_kernel(const float* __restrict__ ebias)
{
    const int n = blockIdx.z;
    const int t0 = blockIdx.y * 128, s0 = blockIdx.x * 128;
    float acc[2][8][4];
#pragma unroll
    for (int i = 0; i < 2; i++)
#pragma unroll
        for (int j = 0; j < 8; j++)
#pragma unroll
            for (int r = 0; r < 4; r++) acc[i][j][r] = 0.f;

    gemm_core<128>(g_qp_h + n * 512 * 64 + t0 * 64,
                   g_qp_l + n * 512 * 64 + t0 * 64, 64,
                   g_kpT_h + n * 64 * 512 + s0,
                   g_kpT_l + n * 64 * 512 + s0, 512, 64, acc);

    const int lane = threadIdx.x & 31, wid = threadIdx.x >> 5;
    const int wm = wid & 3, wn = wid >> 2;
    const float eb = ebias[0];
#pragma unroll
    for (int mt = 0; mt < 2; mt++)
#pragma unroll
        for (int nt = 0; nt < 8; nt++)
#pragma unroll
            for (int r = 0; r < 4; r++) {
                int t = t0 + EPI_ROW(mt, r);
                int s = s0 + EPI_COL(nt, r, 8);
                float e = acc[mt][nt][r] + eb;
                g_p[(n * 512 + t) * 512 + s] = 1.f / (1.f + __expf(-e));
            }
}

// ============================================================================
// Exclusive cumprod of (1-p) along S. grid (512, 128), 512 threads.
// ============================================================================
__global__ __launch_bounds__(512) void cumprod_kernel()
{
    const int s = threadIdx.x;
    const int t = blockIdx.x;
    const int n = blockIdx.y;
    const int idx = (n * 512 + t) * 512 + s;
    const int lane = s & 31, wid = s >> 5;

    __shared__ float wprod[16], wpre[16], incl_sh[512];

    float p = g_p[idx];
    float v = 1.f - p;
#pragma unroll
    for (int o = 1; o < 32; o <<= 1) {
        float u = __shfl_up_sync(0xffffffffu, v, o);
        if (lane >= o) v *= u;
    }
    if (lane == 31) wprod[wid] = v;
    __syncthreads();
    if (wid == 0) {
        float w = (lane < 16) ? wprod[lane] : 1.f;
#pragma unroll
        for (int o = 1; o < 16; o <<= 1) {
            float u = __shfl_up_sync(0xffffffffu, w, o);
            if (lane >= o) w *= u;
        }
        if (lane < 16) wpre[lane] = w;
    }
    __syncthreads();
    float incl = v * (wid > 0 ? wpre[wid - 1] : 1.f);
    incl_sh[s] = incl;
    __syncthreads();
    float cp = (s == 0) ? 1.f : incl_sh[s - 1];
    g_pc[idx] = p * cp;
    g_cl[idx] = fminf(fmaxf(cp, 1e-6f), 1.f);
}

// ============================================================================
// Sequential recurrence over t. One block per n, 512 threads.
// ============================================================================
__global__ __launch_bounds__(512) void recurrence_kernel()
{
    const int s = threadIdx.x;
    const int n = blockIdx.x;
    const int lane = s & 31, wid = s >> 5;
    const int base = n * 512 * 512 + s;

    __shared__ float wsh[16], wpre[16];

    float aprev = (s == 0) ? 1.f : 0.f;
    float pcv = g_pc[base];
    float clv = g_cl[base];

    for (int t = 0; t < 512; t++) {
        float pcn = 0.f, cln = 1.f;
        if (t < 511) {
            pcn = g_pc[base + (t + 1) * 512];
            cln = g_cl[base + (t + 1) * 512];
        }

        float v = aprev / clv;
#pragma unroll
        for (int o = 1; o < 32; o <<= 1) {
            float u = __shfl_up_sync(0xffffffffu, v, o);
            if (lane >= o) v += u;
        }
        if (lane == 31) wsh[wid] = v;
        __syncthreads();
        if (wid == 0) {
            float w = (lane < 16) ? wsh[lane] : 0.f;
#pragma unroll
            for (int o = 1; o < 16; o <<= 1) {
                float u = __shfl_up_sync(0xffffffffu, w, o);
                if (lane >= o) w += u;
            }
            if (lane < 16) wpre[lane] = w;
        }
        __syncthreads();
        float incl = v + (wid > 0 ? wpre[wid - 1] : 0.f);
        float araw = fminf(fmaxf(pcv * incl, 0.f), 1.f);

        float yv = (s < 511) ? araw : 0.f;
#pragma unroll
        for (int o = 16; o > 0; o >>= 1)
            yv += __shfl_xor_sync(0xffffffffu, yv, o);
        if (lane == 0) wsh[wid] = yv;
        __syncthreads();

        float aout = araw;
        if (s == 511) {
            float total = 0.f;
#pragma unroll
            for (int i = 0; i < 16; i++) total += wsh[i];
            aout = 1.f - fminf(fmaxf(total, 0.f), 1.f);
        }
        bf16 hv = __float2bfloat16(aout);
        g_al_h[base + t * 512] = hv;
        g_al_l[base + t * 512] = __float2bfloat16(aout - __bfloat162float(hv));
        __syncthreads();

        aprev = araw;
        pcv = pcn;
        clv = cln;
    }
}

// ============================================================================
// attn = alpha @ vp  (per n: [512x512]@[512x64]) -> merged hi/lo.
// ============================================================================
__global__ __launch_bounds__(256) void attnv_mma_kernel()
{
    const int n = blockIdx.z;
    const int t0 = blockIdx.y * 128;
    float acc[2][4][4];
#pragma unroll
    for (int i = 0; i < 2; i++)
#pragma unroll
        for (int j = 0; j < 4; j++)
#pragma unroll
            for (int r = 0; r < 4; r++) acc[i][j][r] = 0.f;

    gemm_core<64>(g_al_h + n * 512 * 512 + t0 * 512,
                  g_al_l + n * 512 * 512 + t0 * 512, 512,
                  g_vp_h + n * 512 * 64,
                  g_vp_l + n * 512 * 64, 64, 512, acc);

    const int lane = threadIdx.x & 31, wid = threadIdx.x >> 5;
    const int wm = wid & 3, wn = wid >> 2;
    const int b = n >> 4, h = n & 15;
#pragma unroll
    for (int mt = 0; mt < 2; mt++)
#pragma unroll
        for (int nt = 0; nt < 4; nt++)
#pragma unroll
            for (int r = 0; r < 4; r++) {
                int t = t0 + EPI_ROW(mt, r);
                int d = EPI_COL(nt, r, 4);
                int idx = (t * 8 + b) * 1024 + h * 64 + d;
                float v = acc[mt][nt][r];
                bf16 hv = __float2bfloat16(v);
                g_at_h[idx] = hv;
                g_at_l[idx] = __float2bfloat16(v - __bfloat162float(hv));
            }
}

// ============================================================================
// Output projection: out = attn[4096x1024] @ Wo + bo (fp32 out)
// ============================================================================
__global__ __launch_bounds__(256) void out_mma_kernel(
    const float* __restrict__ bias, float* __restrict__ out)
{
    const int bm = blockIdx.y * 128, bn = blockIdx.x * 128;
    float acc[2][8][4];
#pragma unroll
    for (int i = 0; i < 2; i++)
#pragma unroll
        for (int j = 0; j < 8; j++)
#pragma unroll
            for (int r = 0; r < 4; r++) acc[i][j][r] = 0.f;

    gemm_core<128>(g_at_h + bm * 1024, g_at_l + bm * 1024, 1024,
                   g_Wo_h + bn, g_Wo_l + bn, 1024, 1024, acc);

    const int lane = threadIdx.x & 31, wid = threadIdx.x >> 5;
    const int wm = wid & 3, wn = wid >> 2;
#pragma unroll
    for (int mt = 0; mt < 2; mt++)
#pragma unroll
        for (int nt = 0; nt < 8; nt++)
#pragma unroll
            for (int r = 0; r < 4; r++) {
                int row = bm + EPI_ROW(mt, r);
                int col = bn + EPI_COL(nt, r, 8);
                out[row * 1024 + col] = acc[mt][nt][r] + bias[col];
            }
}

// ============================================================================
extern "C" void kernel_launch(void* const* d_in, const int* in_sizes, int n_in,
                              void* d_out, int out_size)
{
    const float* q  = (const float*)d_in[0];
    const float* k  = (const float*)d_in[1];
    const float* v  = (const float*)d_in[2];
    const float* Wq = (const float*)d_in[3];
    const float* Wk = (const float*)d_in[4];
    const float* Wv = (const float*)d_in[5];
    const float* Wo = (const float*)d_in[6];
    const float* bo = (const float*)d_in[7];
    const float* eb = (const float*)d_in[8];
    float* out = (float*)d_out;

    const int NA = MROWS * EMBED;
    const int NW = EMBED * EMBED;
    split_kernel<<<(NA + 255) / 256, 256>>>(q, 0, NA);
    split_kernel<<<(NA + 255) / 256, 256>>>(k, 1, NA);
    split_kernel<<<(NA + 255) / 256, 256>>>(v, 2, NA);
    split_kernel<<<(NW + 255) / 256, 256>>>(Wq, 3, NW);
    split_kernel<<<(NW + 255) / 256, 256>>>(Wk, 4, NW);
    split_kernel<<<(NW + 255) / 256, 256>>>(Wv, 5, NW);
    split_kernel<<<(NW + 255) / 256, 256>>>(Wo, 6, NW);

    dim3 gp(8, 32);
    proj_mma_kernel<<<gp, 256>>>(0.125f, 0);
    proj_mma_kernel<<<gp, 256>>>(1.0f, 1);
    proj_mma_kernel<<<gp, 256>>>(1.0f, 2);

    energy_mma_kernel<<<dim3(4, 4, 128), 256>>>(eb);
    cumprod_kernel<<<dim3(512, 128), 512>>>();
    recurrence_kernel<<<128, 512>>>();
    attnv_mma_kernel<<<dim3(1, 4, 128), 256>>>();
    out_mma_kernel<<<gp, 256>>>(bo, out);
}

// round 4
// speedup vs baseline: 1.5831x; 1.1964x over previous
#include <cuda_runtime.h>
#include <cuda_bf16.h>
#include <cstdint>

typedef __nv_bfloat16 bf16;

#define EMBED 1024
#define TT 512
#define SS 512
#define BATCH 8
#define NHB 128
#define MROWS 4096

// ---------------- scratch (static device globals; no allocation allowed) ----
__device__ bf16 g_q_h[MROWS*EMBED],  g_q_l[MROWS*EMBED];
__device__ bf16 g_k_h[MROWS*EMBED],  g_k_l[MROWS*EMBED];
__device__ bf16 g_v_h[MROWS*EMBED],  g_v_l[MROWS*EMBED];
__device__ bf16 g_Wq_h[EMBED*EMBED], g_Wq_l[EMBED*EMBED];
__device__ bf16 g_Wk_h[EMBED*EMBED], g_Wk_l[EMBED*EMBED];
__device__ bf16 g_Wv_h[EMBED*EMBED], g_Wv_l[EMBED*EMBED];
__device__ bf16 g_Wo_h[EMBED*EMBED], g_Wo_l[EMBED*EMBED];
__device__ bf16 g_qp_h [NHB*TT*64],  g_qp_l [NHB*TT*64];   // [n][t][d]
__device__ bf16 g_kpT_h[NHB*64*SS],  g_kpT_l[NHB*64*SS];   // [n][d][s]
__device__ bf16 g_vp_h [NHB*SS*64],  g_vp_l [NHB*SS*64];   // [n][s][d]
__device__ float g_p [NHB*TT*SS];                          // p_choose (fp32)
__device__ bf16 g_al_h[NHB*TT*SS],   g_al_l[NHB*TT*SS];    // alpha [n][t][s]
__device__ bf16 g_at_h[MROWS*EMBED], g_at_l[MROWS*EMBED];  // merged [t*8+b][h*64+d]

// ============================================================================
// PTX helpers
// ============================================================================
__device__ __forceinline__ uint32_t smem_u32(const void* p) {
    uint32_t a;
    asm("{ .reg .u64 t; cvta.to.shared.u64 t, %1; cvt.u32.u64 %0, t; }"
        : "=r"(a) : "l"(p));
    return a;
}
__device__ __forceinline__ void ldmA(uint32_t r[4], uint32_t addr) {
    asm volatile("ldmatrix.sync.aligned.m8n8.x4.shared.b16 {%0,%1,%2,%3},[%4];"
        : "=r"(r[0]), "=r"(r[1]), "=r"(r[2]), "=r"(r[3]) : "r"(addr));
}
__device__ __forceinline__ void ldmBT(uint32_t r[4], uint32_t addr) {
    asm volatile("ldmatrix.sync.aligned.m8n8.x4.trans.shared.b16 {%0,%1,%2,%3},[%4];"
        : "=r"(r[0]), "=r"(r[1]), "=r"(r[2]), "=r"(r[3]) : "r"(addr));
}
__device__ __forceinline__ void mma16816(float c[4], const uint32_t a[4],
                                         uint32_t b0, uint32_t b1) {
    asm volatile(
        "mma.sync.aligned.m16n8k16.row.col.f32.bf16.bf16.f32 "
        "{%0,%1,%2,%3},{%4,%5,%6,%7},{%8,%9},{%0,%1,%2,%3};"
        : "+f"(c[0]), "+f"(c[1]), "+f"(c[2]), "+f"(c[3])
        : "r"(a[0]), "r"(a[1]), "r"(a[2]), "r"(a[3]), "r"(b0), "r"(b1));
}

// ============================================================================
// bf16x3 GEMM core with fragment reuse.
// acc += Ah*Bh + Ah*Bl + Al*Bh.  Per kk: 12 LDSM instead of 18.
// Block = 128 x BN, 256 threads (8 warps, wm=wid&3, wn=wid>>2).
// ============================================================================
template<int BN>
__device__ __forceinline__ void gemm_core(
    const bf16* __restrict__ Ah, const bf16* __restrict__ Al, int lda,
    const bf16* __restrict__ Bh, const bf16* __restrict__ Bl, int ldb,
    int K, float acc[2][BN/16][4])
{
    constexpr int NT = BN / 16;
    constexpr int BSTR = BN + 40;   // stride = 20 banks mod 32 -> LDSM conflict-free
    __shared__ bf16 sA[2 * 128 * 40];
    __shared__ bf16 sB[2 * 32 * BSTR];
    const int tid = threadIdx.x;
    const int lane = tid & 31, wid = tid >> 5;
    const int wm = wid & 3, wn = wid >> 2;

    for (int k0 = 0; k0 < K; k0 += 32) {
#pragma unroll
        for (int i = 0; i < 2; i++) {
            int id = tid + i * 256;
            int r = id >> 2, cc = (id & 3) * 8;
            *(uint4*)(sA + r * 40 + cc) = *(const uint4*)(Ah + r * lda + k0 + cc);
            *(uint4*)(sA + 128 * 40 + r * 40 + cc) = *(const uint4*)(Al + r * lda + k0 + cc);
        }
        constexpr int BCH = (BN / 8) * 32 / 256;
#pragma unroll
        for (int i = 0; i < BCH; i++) {
            int id = tid + i * 256;
            int r = id / (BN / 8), cc = (id % (BN / 8)) * 8;
            *(uint4*)(sB + r * BSTR + cc) = *(const uint4*)(Bh + (k0 + r) * ldb + cc);
            *(uint4*)(sB + 32 * BSTR + r * BSTR + cc) = *(const uint4*)(Bl + (k0 + r) * ldb + cc);
        }
        __syncthreads();
#pragma unroll
        for (int kk = 0; kk < 32; kk += 16) {
            // --- load Bh fragments (held) ---
            uint32_t bh[NT][2];
#pragma unroll
            for (int np = 0; np < NT / 2; np++) {
                int row = kk + (lane & 15);
                int col = wn * (NT * 8) + np * 16 + ((lane >> 4) << 3);
                uint32_t rr[4];
                ldmBT(rr, smem_u32(sB + row * BSTR + col));
                bh[2 * np][0] = rr[0]; bh[2 * np][1] = rr[1];
                bh[2 * np + 1][0] = rr[2]; bh[2 * np + 1][1] = rr[3];
            }
            // --- load A hi/lo fragments (held) ---
            uint32_t ah[2][4], al[2][4];
#pragma unroll
            for (int mt = 0; mt < 2; mt++) {
                int row = wm * 32 + mt * 16 + (lane & 15);
                int col = kk + ((lane >> 4) << 3);
                ldmA(ah[mt], smem_u32(sA + row * 40 + col));
                ldmA(al[mt], smem_u32(sA + 128 * 40 + row * 40 + col));
            }
            // --- Ah*Bh and Al*Bh ---
#pragma unroll
            for (int mt = 0; mt < 2; mt++)
#pragma unroll
                for (int nt = 0; nt < NT; nt++) {
                    mma16816(acc[mt][nt], ah[mt], bh[nt][0], bh[nt][1]);
                    mma16816(acc[mt][nt], al[mt], bh[nt][0], bh[nt][1]);
                }
            // --- stream Bl, mma with Ah ---
#pragma unroll
            for (int np = 0; np < NT / 2; np++) {
                int row = kk + (lane & 15);
                int col = wn * (NT * 8) + np * 16 + ((lane >> 4) << 3);
                uint32_t rr[4];
                ldmBT(rr, smem_u32(sB + 32 * BSTR + row * BSTR + col));
#pragma unroll
                for (int mt = 0; mt < 2; mt++) {
                    mma16816(acc[mt][2 * np],     ah[mt], rr[0], rr[1]);
                    mma16816(acc[mt][2 * np + 1], ah[mt], rr[2], rr[3]);
                }
            }
        }
        __syncthreads();
    }
}

#define EPI_ROW(mt, r)     (wm * 32 + (mt) * 16 + (lane >> 2) + (((r) >> 1) << 3))
#define EPI_COL(nt, r, NT) (wn * ((NT) * 8) + (nt) * 8 + ((lane & 3) << 1) + ((r) & 1))

// ============================================================================
// split kernels: fp32 -> (bf16 hi, bf16 lo). blockIdx.y selects tensor.
// ============================================================================
__global__ void split_act_kernel(const float* __restrict__ q,
                                 const float* __restrict__ k,
                                 const float* __restrict__ v)
{
    const float* x; bf16 *h, *l;
    switch (blockIdx.y) {
        case 0:  x = q; h = g_q_h; l = g_q_l; break;
        case 1:  x = k; h = g_k_h; l = g_k_l; break;
        default: x = v; h = g_v_h; l = g_v_l; break;
    }
    int i = blockIdx.x * blockDim.x + threadIdx.x;
    float val = x[i];
    bf16 hv = __float2bfloat16(val);
    h[i] = hv;
    l[i] = __float2bfloat16(val - __bfloat162float(hv));
}

__global__ void split_w_kernel(const float* __restrict__ Wq,
                               const float* __restrict__ Wk,
                               const float* __restrict__ Wv,
                               const float* __restrict__ Wo)
{
    const float* x; bf16 *h, *l;
    switch (blockIdx.y) {
        case 0:  x = Wq; h = g_Wq_h; l = g_Wq_l; break;
        case 1:  x = Wk; h = g_Wk_h; l = g_Wk_l; break;
        case 2:  x = Wv; h = g_Wv_h; l = g_Wv_l; break;
        default: x = Wo; h = g_Wo_h; l = g_Wo_l; break;
    }
    int i = blockIdx.x * blockDim.x + threadIdx.x;
    float val = x[i];
    bf16 hv = __float2bfloat16(val);
    h[i] = hv;
    l[i] = __float2bfloat16(val - __bfloat162float(hv));
}

// ============================================================================
// Projection GEMM: [4096x1024] @ [1024x1024], scatter to head-split hi/lo.
// ============================================================================
__global__ __launch_bounds__(256) void proj_mma_kernel(float scale, int which)
{
    const bf16 *Ah, *Al, *Wh, *Wl;
    if (which == 0)      { Ah = g_q_h; Al = g_q_l; Wh = g_Wq_h; Wl = g_Wq_l; }
    else if (which == 1) { Ah = g_k_h; Al = g_k_l; Wh = g_Wk_h; Wl = g_Wk_l; }
    else                 { Ah = g_v_h; Al = g_v_l; Wh = g_Wv_h; Wl = g_Wv_l; }

    const int bm = blockIdx.y * 128, bn = blockIdx.x * 128;
    float acc[2][8][4];
#pragma unroll
    for (int i = 0; i < 2; i++)
#pragma unroll
        for (int j = 0; j < 8; j++)
#pragma unroll
            for (int r = 0; r < 4; r++) acc[i][j][r] = 0.f;

    gemm_core<128>(Ah + bm * 1024, Al + bm * 1024, 1024,
                   Wh + bn, Wl + bn, 1024, 1024, acc);

    const int lane = threadIdx.x & 31, wid = threadIdx.x >> 5;
    const int wm = wid & 3, wn = wid >> 2;
    bf16 *dh, *dl;
    if (which == 0)      { dh = g_qp_h;  dl = g_qp_l;  }
    else if (which == 1) { dh = g_kpT_h; dl = g_kpT_l; }
    else                 { dh = g_vp_h;  dl = g_vp_l;  }

#pragma unroll
    for (int mt = 0; mt < 2; mt++)
#pragma unroll
        for (int nt = 0; nt < 8; nt++)
#pragma unroll
            for (int r = 0; r < 4; r++) {
                int row = bm + EPI_ROW(mt, r);
                int col = bn + EPI_COL(nt, r, 8);
                int t = row >> 3, b = row & 7;
                int h = col >> 6, d = col & 63;
                int n = b * 16 + h;
                float v = acc[mt][nt][r] * scale;
                int idx = (which == 1) ? (n * 64 + d) * 512 + t
                                       : (n * 512 + t) * 64 + d;
                bf16 hv = __float2bfloat16(v);
                dh[idx] = hv;
                dl[idx] = __float2bfloat16(v - __bfloat162float(hv));
            }
}

// ============================================================================
// Energy + sigmoid -> g_p (fp32)
// ============================================================================
__global__ __launch_bounds__(256) void energy_mma_kernel(const float* __restrict__ ebias)
{
    const int n = blockIdx.z;
    const int t0 = blockIdx.y * 128, s0 = blockIdx.x * 128;
    float acc[2][8][4];
#pragma unroll
    for (int i = 0; i < 2; i++)
#pragma unroll
        for (int j = 0; j < 8; j++)
#pragma unroll
            for (int r = 0; r < 4; r++) acc[i][j][r] = 0.f;

    gemm_core<128>(g_qp_h + n * 512 * 64 + t0 * 64,
                   g_qp_l + n * 512 * 64 + t0 * 64, 64,
                   g_kpT_h + n * 64 * 512 + s0,
                   g_kpT_l + n * 64 * 512 + s0, 512, 64, acc);

    const int lane = threadIdx.x & 31, wid = threadIdx.x >> 5;
    const int wm = wid & 3, wn = wid >> 2;
    const float eb = ebias[0];
#pragma unroll
    for (int mt = 0; mt < 2; mt++)
#pragma unroll
        for (int nt = 0; nt < 8; nt++)
#pragma unroll
            for (int r = 0; r < 4; r++) {
                int t = t0 + EPI_ROW(mt, r);
                int s = s0 + EPI_COL(nt, r, 8);
                float e = acc[mt][nt][r] + eb;
                g_p[(n * 512 + t) * 512 + s] = 1.f / (1.f + __expf(-e));
            }
}

// ============================================================================
// Fused recurrence: per t, compute exclusive cumprod of (1-p) (block product
// scan), then the alpha recurrence (block sum scan), then mass-preservation.
// One block per n (128 blocks), 512 threads (one per s).
// ============================================================================
__global__ __launch_bounds__(512) void recurrence_kernel()
{
    const int s = threadIdx.x;
    const int n = blockIdx.x;
    const int lane = s & 31, wid = s >> 5;
    const int base = n * 512 * 512 + s;

    __shared__ float sh_pw[16], sh_pp[16];  // product scan warp totals / prefix
    __shared__ float sh_sw[16], sh_sp[16];  // sum scan warp totals / prefix
    __shared__ float sh_m[16];              // mass reduction

    float aprev = (s == 0) ? 1.f : 0.f;
    float p = g_p[base];

    for (int t = 0; t < 512; t++) {
        float pnext = (t < 511) ? g_p[base + (t + 1) * 512] : 0.f;

        // ---- exclusive cumprod of (1-p) along s ----
        float v = 1.f - p;
#pragma unroll
        for (int o = 1; o < 32; o <<= 1) {
            float u = __shfl_up_sync(0xffffffffu, v, o);
            if (lane >= o) v *= u;
        }
        if (lane == 31) sh_pw[wid] = v;
        __syncthreads();
        if (wid == 0) {
            float w = (lane < 16) ? sh_pw[lane] : 1.f;
#pragma unroll
            for (int o = 1; o < 16; o <<= 1) {
                float u = __shfl_up_sync(0xffffffffu, w, o);
                if (lane >= o) w *= u;
            }
            if (lane < 16) sh_pp[lane] = w;
        }
        __syncthreads();
        float woff = (wid > 0) ? sh_pp[wid - 1] : 1.f;
        float inclp = v * woff;
        float cp = __shfl_up_sync(0xffffffffu, inclp, 1);
        if (lane == 0) cp = woff;           // product of all preceding warps
        if (s == 0) cp = 1.f;               // exclusive: first element = 1
        float cl = fminf(fmaxf(cp, 1e-6f), 1.f);
        float pc = p * cp;

        // ---- sum scan of aprev / cl ----
        float u2 = aprev / cl;
#pragma unroll
        for (int o = 1; o < 32; o <<= 1) {
            float uu = __shfl_up_sync(0xffffffffu, u2, o);
            if (lane >= o) u2 += uu;
        }
        if (lane == 31) sh_sw[wid] = u2;
        __syncthreads();
        if (wid == 0) {
            float w = (lane < 16) ? sh_sw[lane] : 0.f;
#pragma unroll
            for (int o = 1; o < 16; o <<= 1) {
                float uu = __shfl_up_sync(0xffffffffu, w, o);
                if (lane >= o) w += uu;
            }
            if (lane < 16) sh_sp[lane] = w;
        }
        __syncthreads();
        float incl2 = u2 + ((wid > 0) ? sh_sp[wid - 1] : 0.f);
        float araw = fminf(fmaxf(pc * incl2, 0.f), 1.f);

        // ---- mass preservation on last column ----
        float yv = (s < 511) ? araw : 0.f;
#pragma unroll
        for (int o = 16; o > 0; o >>= 1)
            yv += __shfl_xor_sync(0xffffffffu, yv, o);
        if (lane == 0) sh_m[wid] = yv;
        __syncthreads();

        float aout = araw;
        if (s == 511) {
            float total = 0.f;
#pragma unroll
            for (int i = 0; i < 16; i++) total += sh_m[i];
            aout = 1.f - fminf(fmaxf(total, 0.f), 1.f);
        }
        bf16 hv = __float2bfloat16(aout);
        g_al_h[base + t * 512] = hv;
        g_al_l[base + t * 512] = __float2bfloat16(aout - __bfloat162float(hv));

        aprev = araw;
        p = pnext;
    }
}

// ============================================================================
// attn = alpha @ vp  (per n: [512x512]@[512x64]) -> merged hi/lo.
// ============================================================================
__global__ __launch_bounds__(256) void attnv_mma_kernel()
{
    const int n = blockIdx.z;
    const int t0 = blockIdx.y * 128;
    float acc[2][4][4];
#pragma unroll
    for (int i = 0; i < 2; i++)
#pragma unroll
        for (int j = 0; j < 4; j++)
#pragma unroll
            for (int r = 0; r < 4; r++) acc[i][j][r] = 0.f;

    gemm_core<64>(g_al_h + n * 512 * 512 + t0 * 512,
                  g_al_l + n * 512 * 512 + t0 * 512, 512,
                  g_vp_h + n * 512 * 64,
                  g_vp_l + n * 512 * 64, 64, 512, acc);

    const int lane = threadIdx.x & 31, wid = threadIdx.x >> 5;
    const int wm = wid & 3, wn = wid >> 2;
    const int b = n >> 4, h = n & 15;
#pragma unroll
    for (int mt = 0; mt < 2; mt++)
#pragma unroll
        for (int nt = 0; nt < 4; nt++)
#pragma unroll
            for (int r = 0; r < 4; r++) {
                int t = t0 + EPI_ROW(mt, r);
                int d = EPI_COL(nt, r, 4);
                int idx = (t * 8 + b) * 1024 + h * 64 + d;
                float v = acc[mt][nt][r];
                bf16 hv = __float2bfloat16(v);
                g_at_h[idx] = hv;
                g_at_l[idx] = __float2bfloat16(v - __bfloat162float(hv));
            }
}

// ============================================================================
// Output projection: out = attn[4096x1024] @ Wo + bo (fp32 out)
// ============================================================================
__global__ __launch_bounds__(256) void out_mma_kernel(
    const float* __restrict__ bias, float* __restrict__ out)
{
    const int bm = blockIdx.y * 128, bn = blockIdx.x * 128;
    float acc[2][8][4];
#pragma unroll
    for (int i = 0; i < 2; i++)
#pragma unroll
        for (int j = 0; j < 8; j++)
#pragma unroll
            for (int r = 0; r < 4; r++) acc[i][j][r] = 0.f;

    gemm_core<128>(g_at_h + bm * 1024, g_at_l + bm * 1024, 1024,
                   g_Wo_h + bn, g_Wo_l + bn, 1024, 1024, acc);

    const int lane = threadIdx.x & 31, wid = threadIdx.x >> 5;
    const int wm = wid & 3, wn = wid >> 2;
#pragma unroll
    for (int mt = 0; mt < 2; mt++)
#pragma unroll
        for (int nt = 0; nt < 8; nt++)
#pragma unroll
            for (int r = 0; r < 4; r++) {
                int row = bm + EPI_ROW(mt, r);
                int col = bn + EPI_COL(nt, r, 8);
                out[row * 1024 + col] = acc[mt][nt][r] + bias[col];
            }
}

// ============================================================================
extern "C" void kernel_launch(void* const* d_in, const int* in_sizes, int n_in,
                              void* d_out, int out_size)
{
    const float* q  = (const float*)d_in[0];
    const float* k  = (const float*)d_in[1];
    const float* v  = (const float*)d_in[2];
    const float* Wq = (const float*)d_in[3];
    const float* Wk = (const float*)d_in[4];
    const float* Wv = (const float*)d_in[5];
    const float* Wo = (const float*)d_in[6];
    const float* bo = (const float*)d_in[7];
    const float* eb = (const float*)d_in[8];
    float* out = (float*)d_out;

    split_act_kernel<<<dim3(MROWS * EMBED / 256, 3), 256>>>(q, k, v);
    split_w_kernel<<<dim3(EMBED * EMBED / 256, 4), 256>>>(Wq, Wk, Wv, Wo);

    dim3 gp(8, 32);
    proj_mma_kernel<<<gp, 256>>>(0.125f, 0);
    proj_mma_kernel<<<gp, 256>>>(1.0f, 1);
    proj_mma_kernel<<<gp, 256>>>(1.0f, 2);

    energy_mma_kernel<<<dim3(4, 4, 128), 256>>>(eb);
    recurrence_kernel<<<128, 512>>>();
    attnv_mma_kernel<<<dim3(1, 4, 128), 256>>>();
    out_mma_kernel<<<gp, 256>>>(bo, out);
}

// round 5
// speedup vs baseline: 1.8164x; 1.1474x over previous
#include <cuda_runtime.h>
#include <cuda_bf16.h>
#include <cstdint>

typedef __nv_bfloat16 bf16;

#define EMBED 1024
#define TT 512
#define SS 512
#define BATCH 8
#define NHB 128
#define MROWS 4096

// ---------------- scratch (static device globals; no allocation allowed) ----
__device__ bf16 g_q_h[MROWS*EMBED],  g_q_l[MROWS*EMBED];
__device__ bf16 g_k_h[MROWS*EMBED],  g_k_l[MROWS*EMBED];
__device__ bf16 g_v_h[MROWS*EMBED],  g_v_l[MROWS*EMBED];
__device__ bf16 g_Wq_h[EMBED*EMBED], g_Wq_l[EMBED*EMBED];
__device__ bf16 g_Wk_h[EMBED*EMBED], g_Wk_l[EMBED*EMBED];
__device__ bf16 g_Wv_h[EMBED*EMBED], g_Wv_l[EMBED*EMBED];
__device__ bf16 g_Wo_h[EMBED*EMBED], g_Wo_l[EMBED*EMBED];
__device__ bf16 g_qp_h [NHB*TT*64],  g_qp_l [NHB*TT*64];   // [n][t][d]
__device__ bf16 g_kpT_h[NHB*64*SS],  g_kpT_l[NHB*64*SS];   // [n][d][s]
__device__ bf16 g_vp_h [NHB*SS*64],  g_vp_l [NHB*SS*64];   // [n][s][d]
__device__ float g_p [NHB*TT*SS];                          // p_choose (fp32)
__device__ bf16 g_al_h[NHB*TT*SS],   g_al_l[NHB*TT*SS];    // alpha [n][t][s]
__device__ bf16 g_at_h[MROWS*EMBED], g_at_l[MROWS*EMBED];  // merged [t*8+b][h*64+d]

// ============================================================================
// PTX helpers
// ============================================================================
__device__ __forceinline__ uint32_t smem_u32(const void* p) {
    uint32_t a;
    asm("{ .reg .u64 t; cvta.to.shared.u64 t, %1; cvt.u32.u64 %0, t; }"
        : "=r"(a) : "l"(p));
    return a;
}
__device__ __forceinline__ void ldmA(uint32_t r[4], uint32_t addr) {
    asm volatile("ldmatrix.sync.aligned.m8n8.x4.shared.b16 {%0,%1,%2,%3},[%4];"
        : "=r"(r[0]), "=r"(r[1]), "=r"(r[2]), "=r"(r[3]) : "r"(addr));
}
__device__ __forceinline__ void ldmBT(uint32_t r[4], uint32_t addr) {
    asm volatile("ldmatrix.sync.aligned.m8n8.x4.trans.shared.b16 {%0,%1,%2,%3},[%4];"
        : "=r"(r[0]), "=r"(r[1]), "=r"(r[2]), "=r"(r[3]) : "r"(addr));
}
__device__ __forceinline__ void mma16816(float c[4], const uint32_t a[4],
                                         uint32_t b0, uint32_t b1) {
    asm volatile(
        "mma.sync.aligned.m16n8k16.row.col.f32.bf16.bf16.f32 "
        "{%0,%1,%2,%3},{%4,%5,%6,%7},{%8,%9},{%0,%1,%2,%3};"
        : "+f"(c[0]), "+f"(c[1]), "+f"(c[2]), "+f"(c[3])
        : "r"(a[0]), "r"(a[1]), "r"(a[2]), "r"(a[3]), "r"(b0), "r"(b1));
}
__device__ __forceinline__ void cp16(uint32_t dst, const void* src) {
    asm volatile("cp.async.ca.shared.global [%0], [%1], 16;"
        :: "r"(dst), "l"(src));
}
__device__ __forceinline__ void cp_commit() {
    asm volatile("cp.async.commit_group;");
}
template<int N>
__device__ __forceinline__ void cp_wait() {
    asm volatile("cp.async.wait_group %0;" :: "n"(N));
}

// ============================================================================
// bf16x3 GEMM core, cp.async double-buffered, fragment reuse.
// acc += Ah*Bh + Ah*Bl + Al*Bh.
// Block = 128 x BN, 256 threads (8 warps, wm=wid&3, wn=wid>>2).
// ============================================================================
template<int BN>
__device__ __forceinline__ void gemm_core(
    const bf16* __restrict__ Ah, const bf16* __restrict__ Al, int lda,
    const bf16* __restrict__ Bh, const bf16* __restrict__ Bl, int ldb,
    int K, float acc[2][BN/16][4])
{
    constexpr int NT = BN / 16;
    constexpr int BSTR = BN + 40;         // 20 banks mod 32 -> LDSM conflict-free
    constexpr int ASZ = 2 * 128 * 40;     // hi+lo per stage
    constexpr int BSZ = 2 * 32 * BSTR;
    __shared__ bf16 sA[2 * ASZ];
    __shared__ bf16 sB[2 * BSZ];
    const int tid = threadIdx.x;
    const int lane = tid & 31, wid = tid >> 5;
    const int wm = wid & 3, wn = wid >> 2;
    const int nTiles = K / 32;

    // per-thread load coordinates
    const int aR = tid >> 2, aC = (tid & 3) * 8;
    constexpr int BCH = (BN / 8) * 32 / 256;

    auto loadTile = [&](int st, int k0) {
        bf16* dA = sA + st * ASZ;
        cp16(smem_u32(dA + aR * 40 + aC), Ah + aR * lda + k0 + aC);
        cp16(smem_u32(dA + 128 * 40 + aR * 40 + aC), Al + aR * lda + k0 + aC);
        {
            int id = tid + 256;
            int r = id >> 2, cc = (id & 3) * 8;
            cp16(smem_u32(dA + r * 40 + cc), Ah + r * lda + k0 + cc);
            cp16(smem_u32(dA + 128 * 40 + r * 40 + cc), Al + r * lda + k0 + cc);
        }
        bf16* dB = sB + st * BSZ;
#pragma unroll
        for (int i = 0; i < BCH; i++) {
            int id = tid + i * 256;
            int r = id / (BN / 8), cc = (id % (BN / 8)) * 8;
            cp16(smem_u32(dB + r * BSTR + cc), Bh + (k0 + r) * ldb + cc);
            cp16(smem_u32(dB + 32 * BSTR + r * BSTR + cc), Bl + (k0 + r) * ldb + cc);
        }
    };

    loadTile(0, 0);
    cp_commit();

    for (int i = 0; i < nTiles; i++) {
        if (i + 1 < nTiles) {
            loadTile((i + 1) & 1, (i + 1) * 32);
            cp_commit();
            cp_wait<1>();
        } else {
            cp_wait<0>();
        }
        __syncthreads();

        const bf16* pA = sA + (i & 1) * ASZ;
        const bf16* pB = sB + (i & 1) * BSZ;
#pragma unroll
        for (int kk = 0; kk < 32; kk += 16) {
            uint32_t bh[NT][2];
#pragma unroll
            for (int np = 0; np < NT / 2; np++) {
                int row = kk + (lane & 15);
                int col = wn * (NT * 8) + np * 16 + ((lane >> 4) << 3);
                uint32_t rr[4];
                ldmBT(rr, smem_u32(pB + row * BSTR + col));
                bh[2 * np][0] = rr[0]; bh[2 * np][1] = rr[1];
                bh[2 * np + 1][0] = rr[2]; bh[2 * np + 1][1] = rr[3];
            }
            uint32_t ah[2][4], al[2][4];
#pragma unroll
            for (int mt = 0; mt < 2; mt++) {
                int row = wm * 32 + mt * 16 + (lane & 15);
                int col = kk + ((lane >> 4) << 3);
                ldmA(ah[mt], smem_u32(pA + row * 40 + col));
                ldmA(al[mt], smem_u32(pA + 128 * 40 + row * 40 + col));
            }
#pragma unroll
            for (int mt = 0; mt < 2; mt++)
#pragma unroll
                for (int nt = 0; nt < NT; nt++) {
                    mma16816(acc[mt][nt], ah[mt], bh[nt][0], bh[nt][1]);
                    mma16816(acc[mt][nt], al[mt], bh[nt][0], bh[nt][1]);
                }
#pragma unroll
            for (int np = 0; np < NT / 2; np++) {
                int row = kk + (lane & 15);
                int col = wn * (NT * 8) + np * 16 + ((lane >> 4) << 3);
                uint32_t rr[4];
                ldmBT(rr, smem_u32(pB + 32 * BSTR + row * BSTR + col));
#pragma unroll
                for (int mt = 0; mt < 2; mt++) {
                    mma16816(acc[mt][2 * np],     ah[mt], rr[0], rr[1]);
                    mma16816(acc[mt][2 * np + 1], ah[mt], rr[2], rr[3]);
                }
            }
        }
        __syncthreads();
    }
}

#define EPI_ROW(mt, r)     (wm * 32 + (mt) * 16 + (lane >> 2) + (((r) >> 1) << 3))
#define EPI_COL(nt, r, NT) (wn * ((NT) * 8) + (nt) * 8 + ((lane & 3) << 1) + ((r) & 1))

// ============================================================================
// split kernels: fp32 -> (bf16 hi, bf16 lo). blockIdx.y selects tensor.
// ============================================================================
__global__ void split_act_kernel(const float* __restrict__ q,
                                 const float* __restrict__ k,
                                 const float* __restrict__ v)
{
    const float* x; bf16 *h, *l;
    switch (blockIdx.y) {
        case 0:  x = q; h = g_q_h; l = g_q_l; break;
        case 1:  x = k; h = g_k_h; l = g_k_l; break;
        default: x = v; h = g_v_h; l = g_v_l; break;
    }
    int i = blockIdx.x * blockDim.x + threadIdx.x;
    float val = x[i];
    bf16 hv = __float2bfloat16(val);
    h[i] = hv;
    l[i] = __float2bfloat16(val - __bfloat162float(hv));
}

__global__ void split_w_kernel(const float* __restrict__ Wq,
                               const float* __restrict__ Wk,
                               const float* __restrict__ Wv,
                               const float* __restrict__ Wo)
{
    const float* x; bf16 *h, *l;
    switch (blockIdx.y) {
        case 0:  x = Wq; h = g_Wq_h; l = g_Wq_l; break;
        case 1:  x = Wk; h = g_Wk_h; l = g_Wk_l; break;
        case 2:  x = Wv; h = g_Wv_h; l = g_Wv_l; break;
        default: x = Wo; h = g_Wo_h; l = g_Wo_l; break;
    }
    int i = blockIdx.x * blockDim.x + threadIdx.x;
    float val = x[i];
    bf16 hv = __float2bfloat16(val);
    h[i] = hv;
    l[i] = __float2bfloat16(val - __bfloat162float(hv));
}

// ============================================================================
// Merged projection GEMM: blockIdx.z = which (0=Q,1=K,2=V).
// [4096x1024] @ [1024x1024] -> head-split hi/lo.
// ============================================================================
__global__ __launch_bounds__(256) void proj_mma_kernel()
{
    const int which = blockIdx.z;
    const bf16 *Ah, *Al, *Wh, *Wl;
    if (which == 0)      { Ah = g_q_h; Al = g_q_l; Wh = g_Wq_h; Wl = g_Wq_l; }
    else if (which == 1) { Ah = g_k_h; Al = g_k_l; Wh = g_Wk_h; Wl = g_Wk_l; }
    else                 { Ah = g_v_h; Al = g_v_l; Wh = g_Wv_h; Wl = g_Wv_l; }
    const float scale = (which == 0) ? 0.125f : 1.0f;

    const int bm = blockIdx.y * 128, bn = blockIdx.x * 128;
    float acc[2][8][4];
#pragma unroll
    for (int i = 0; i < 2; i++)
#pragma unroll
        for (int j = 0; j < 8; j++)
#pragma unroll
            for (int r = 0; r < 4; r++) acc[i][j][r] = 0.f;

    gemm_core<128>(Ah + bm * 1024, Al + bm * 1024, 1024,
                   Wh + bn, Wl + bn, 1024, 1024, acc);

    const int lane = threadIdx.x & 31, wid = threadIdx.x >> 5;
    const int wm = wid & 3, wn = wid >> 2;
    bf16 *dh, *dl;
    if (which == 0)      { dh = g_qp_h;  dl = g_qp_l;  }
    else if (which == 1) { dh = g_kpT_h; dl = g_kpT_l; }
    else                 { dh = g_vp_h;  dl = g_vp_l;  }

#pragma unroll
    for (int mt = 0; mt < 2; mt++)
#pragma unroll
        for (int nt = 0; nt < 8; nt++)
#pragma unroll
            for (int r = 0; r < 4; r++) {
                int row = bm + EPI_ROW(mt, r);
                int col = bn + EPI_COL(nt, r, 8);
                int t = row >> 3, b = row & 7;
                int h = col >> 6, d = col & 63;
                int n = b * 16 + h;
                float v = acc[mt][nt][r] * scale;
                int idx = (which == 1) ? (n * 64 + d) * 512 + t
                                       : (n * 512 + t) * 64 + d;
                bf16 hv = __float2bfloat16(v);
                dh[idx] = hv;
                dl[idx] = __float2bfloat16(v - __bfloat162float(hv));
            }
}

// ============================================================================
// Energy + sigmoid -> g_p (fp32)
// ============================================================================
__global__ __launch_bounds__(256) void energy_mma_kernel(const float* __restrict__ ebias)
{
    const int n = blockIdx.z;
    const int t0 = blockIdx.y * 128, s0 = blockIdx.x * 128;
    float acc[2][8][4];
#pragma unroll
    for (int i = 0; i < 2; i++)
#pragma unroll
        for (int j = 0; j < 8; j++)
#pragma unroll
            for (int r = 0; r < 4; r++) acc[i][j][r] = 0.f;

    gemm_core<128>(g_qp_h + n * 512 * 64 + t0 * 64,
                   g_qp_l + n * 512 * 64 + t0 * 64, 64,
                   g_kpT_h + n * 64 * 512 + s0,
                   g_kpT_l + n * 64 * 512 + s0, 512, 64, acc);

    const int lane = threadIdx.x & 31, wid = threadIdx.x >> 5;
    const int wm = wid & 3, wn = wid >> 2;
    const float eb = ebias[0];
#pragma unroll
    for (int mt = 0; mt < 2; mt++)
#pragma unroll
        for (int nt = 0; nt < 8; nt++)
#pragma unroll
            for (int r = 0; r < 4; r++) {
                int t = t0 + EPI_ROW(mt, r);
                int s = s0 + EPI_COL(nt, r, 8);
                float e = acc[mt][nt][r] + eb;
                g_p[(n * 512 + t) * 512 + s] = 1.f / (1.f + __expf(-e));
            }
}

// ============================================================================
// Fused recurrence (cumprod + alpha scan + mass preservation).
// One block per n (128 blocks), 512 threads (one per s).
// ============================================================================
__global__ __launch_bounds__(512) void recurrence_kernel()
{
    const int s = threadIdx.x;
    const int n = blockIdx.x;
    const int lane = s & 31, wid = s >> 5;
    const int base = n * 512 * 512 + s;

    __shared__ float sh_pw[16], sh_pp[16];
    __shared__ float sh_sw[16], sh_sp[16];
    __shared__ float sh_m[16];

    float aprev = (s == 0) ? 1.f : 0.f;
    float p = g_p[base];

    for (int t = 0; t < 512; t++) {
        float pnext = (t < 511) ? g_p[base + (t + 1) * 512] : 0.f;

        // ---- exclusive cumprod of (1-p) ----
        float v = 1.f - p;
#pragma unroll
        for (int o = 1; o < 32; o <<= 1) {
            float u = __shfl_up_sync(0xffffffffu, v, o);
            if (lane >= o) v *= u;
        }
        if (lane == 31) sh_pw[wid] = v;
        __syncthreads();
        if (wid == 0) {
            float w = (lane < 16) ? sh_pw[lane] : 1.f;
#pragma unroll
            for (int o = 1; o < 16; o <<= 1) {
                float u = __shfl_up_sync(0xffffffffu, w, o);
                if (lane >= o) w *= u;
            }
            if (lane < 16) sh_pp[lane] = w;
        }
        __syncthreads();
        float woff = (wid > 0) ? sh_pp[wid - 1] : 1.f;
        float inclp = v * woff;
        float cp = __shfl_up_sync(0xffffffffu, inclp, 1);
        if (lane == 0) cp = woff;
        if (s == 0) cp = 1.f;
        float cl = fminf(fmaxf(cp, 1e-6f), 1.f);
        float pc = p * cp;

        // ---- sum scan of aprev / cl ----
        float u2 = aprev / cl;
#pragma unroll
        for (int o = 1; o < 32; o <<= 1) {
            float uu = __shfl_up_sync(0xffffffffu, u2, o);
            if (lane >= o) u2 += uu;
        }
        if (lane == 31) sh_sw[wid] = u2;
        __syncthreads();
        if (wid == 0) {
            float w = (lane < 16) ? sh_sw[lane] : 0.f;
#pragma unroll
            for (int o = 1; o < 16; o <<= 1) {
                float uu = __shfl_up_sync(0xffffffffu, w, o);
                if (lane >= o) w += uu;
            }
            if (lane < 16) sh_sp[lane] = w;
        }
        __syncthreads();
        float incl2 = u2 + ((wid > 0) ? sh_sp[wid - 1] : 0.f);
        float araw = fminf(fmaxf(pc * incl2, 0.f), 1.f);

        // ---- mass preservation on last column ----
        float yv = (s < 511) ? araw : 0.f;
#pragma unroll
        for (int o = 16; o > 0; o >>= 1)
            yv += __shfl_xor_sync(0xffffffffu, yv, o);
        if (lane == 0) sh_m[wid] = yv;
        __syncthreads();

        float aout = araw;
        if (s == 511) {
            float total = 0.f;
#pragma unroll
            for (int i = 0; i < 16; i++) total += sh_m[i];
            aout = 1.f - fminf(fmaxf(total, 0.f), 1.f);
        }
        bf16 hv = __float2bfloat16(aout);
        g_al_h[base + t * 512] = hv;
        g_al_l[base + t * 512] = __float2bfloat16(aout - __bfloat162float(hv));

        aprev = araw;
        p = pnext;
    }
}

// ============================================================================
// attn = alpha @ vp  (per n: [512x512]@[512x64]) -> merged hi/lo.
// ============================================================================
__global__ __launch_bounds__(256) void attnv_mma_kernel()
{
    const int n = blockIdx.z;
    const int t0 = blockIdx.y * 128;
    float acc[2][4][4];
#pragma unroll
    for (int i = 0; i < 2; i++)
#pragma unroll
        for (int j = 0; j < 4; j++)
#pragma unroll
            for (int r = 0; r < 4; r++) acc[i][j][r] = 0.f;

    gemm_core<64>(g_al_h + n * 512 * 512 + t0 * 512,
                  g_al_l + n * 512 * 512 + t0 * 512, 512,
                  g_vp_h + n * 512 * 64,
                  g_vp_l + n * 512 * 64, 64, 512, acc);

    const int lane = threadIdx.x & 31, wid = threadIdx.x >> 5;
    const int wm = wid & 3, wn = wid >> 2;
    const int b = n >> 4, h = n & 15;
#pragma unroll
    for (int mt = 0; mt < 2; mt++)
#pragma unroll
        for (int nt = 0; nt < 4; nt++)
#pragma unroll
            for (int r = 0; r < 4; r++) {
                int t = t0 + EPI_ROW(mt, r);
                int d = EPI_COL(nt, r, 4);
                int idx = (t * 8 + b) * 1024 + h * 64 + d;
                float v = acc[mt][nt][r];
                bf16 hv = __float2bfloat16(v);
                g_at_h[idx] = hv;
                g_at_l[idx] = __float2bfloat16(v - __bfloat162float(hv));
            }
}

// ============================================================================
// Output projection: out = attn[4096x1024] @ Wo + bo (fp32 out)
// ============================================================================
__global__ __launch_bounds__(256) void out_mma_kernel(
    const float* __restrict__ bias, float* __restrict__ out)
{
    const int bm = blockIdx.y * 128, bn = blockIdx.x * 128;
    float acc[2][8][4];
#pragma unroll
    for (int i = 0; i < 2; i++)
#pragma unroll
        for (int j = 0; j < 8; j++)
#pragma unroll
            for (int r = 0; r < 4; r++) acc[i][j][r] = 0.f;

    gemm_core<128>(g_at_h + bm * 1024, g_at_l + bm * 1024, 1024,
                   g_Wo_h + bn, g_Wo_l + bn, 1024, 1024, acc);

    const int lane = threadIdx.x & 31, wid = threadIdx.x >> 5;
    const int wm = wid & 3, wn = wid >> 2;
#pragma unroll
    for (int mt = 0; mt < 2; mt++)
#pragma unroll
        for (int nt = 0; nt < 8; nt++)
#pragma unroll
            for (int r = 0; r < 4; r++) {
                int row = bm + EPI_ROW(mt, r);
                int col = bn + EPI_COL(nt, r, 8);
                out[row * 1024 + col] = acc[mt][nt][r] + bias[col];
            }
}

// ============================================================================
extern "C" void kernel_launch(void* const* d_in, const int* in_sizes, int n_in,
                              void* d_out, int out_size)
{
    const float* q  = (const float*)d_in[0];
    const float* k  = (const float*)d_in[1];
    const float* v  = (const float*)d_in[2];
    const float* Wq = (const float*)d_in[3];
    const float* Wk = (const float*)d_in[4];
    const float* Wv = (const float*)d_in[5];
    const float* Wo = (const float*)d_in[6];
    const float* bo = (const float*)d_in[7];
    const float* eb = (const float*)d_in[8];
    float* out = (float*)d_out;

    split_act_kernel<<<dim3(MROWS * EMBED / 256, 3), 256>>>(q, k, v);
    split_w_kernel<<<dim3(EMBED * EMBED / 256, 4), 256>>>(Wq, Wk, Wv, Wo);

    proj_mma_kernel<<<dim3(8, 32, 3), 256>>>();
    energy_mma_kernel<<<dim3(4, 4, 128), 256>>>(eb);
    recurrence_kernel<<<128, 512>>>();
    attnv_mma_kernel<<<dim3(1, 4, 128), 256>>>();
    out_mma_kernel<<<dim3(8, 32), 256>>>(bo, out);
}

// round 6
// speedup vs baseline: 1.8500x; 1.0185x over previous
#include <cuda_runtime.h>
#include <cuda_bf16.h>
#include <cstdint>

typedef __nv_bfloat16 bf16;

#define EMBED 1024
#define TT 512
#define SS 512
#define BATCH 8
#define NHB 128
#define MROWS 4096

// ---------------- scratch (static device globals; no allocation allowed) ----
__device__ bf16 g_q_h[MROWS*EMBED],  g_q_l[MROWS*EMBED];
__device__ bf16 g_k_h[MROWS*EMBED],  g_k_l[MROWS*EMBED];
__device__ bf16 g_v_h[MROWS*EMBED],  g_v_l[MROWS*EMBED];
__device__ bf16 g_Wq_h[EMBED*EMBED], g_Wq_l[EMBED*EMBED];
__device__ bf16 g_Wk_h[EMBED*EMBED], g_Wk_l[EMBED*EMBED];
__device__ bf16 g_Wv_h[EMBED*EMBED], g_Wv_l[EMBED*EMBED];
__device__ bf16 g_Wo_h[EMBED*EMBED], g_Wo_l[EMBED*EMBED];
__device__ bf16 g_qp_h [NHB*TT*64],  g_qp_l [NHB*TT*64];   // [n][t][d]
__device__ bf16 g_kpT_h[NHB*64*SS],  g_kpT_l[NHB*64*SS];   // [n][d][s]
__device__ bf16 g_vp_h [NHB*SS*64],  g_vp_l [NHB*SS*64];   // [n][s][d]
__device__ float g_p [NHB*TT*SS];                          // p_choose (fp32)
__device__ bf16 g_al_h[NHB*TT*SS],   g_al_l[NHB*TT*SS];    // alpha [n][t][s]
__device__ bf16 g_at_h[MROWS*EMBED], g_at_l[MROWS*EMBED];  // merged [t*8+b][h*64+d]

// ============================================================================
// PTX helpers
// ============================================================================
__device__ __forceinline__ uint32_t smem_u32(const void* p) {
    uint32_t a;
    asm("{ .reg .u64 t; cvta.to.shared.u64 t, %1; cvt.u32.u64 %0, t; }"
        : "=r"(a) : "l"(p));
    return a;
}
__device__ __forceinline__ void ldmA(uint32_t r[4], uint32_t addr) {
    asm volatile("ldmatrix.sync.aligned.m8n8.x4.shared.b16 {%0,%1,%2,%3},[%4];"
        : "=r"(r[0]), "=r"(r[1]), "=r"(r[2]), "=r"(r[3]) : "r"(addr));
}
__device__ __forceinline__ void ldmBT(uint32_t r[4], uint32_t addr) {
    asm volatile("ldmatrix.sync.aligned.m8n8.x4.trans.shared.b16 {%0,%1,%2,%3},[%4];"
        : "=r"(r[0]), "=r"(r[1]), "=r"(r[2]), "=r"(r[3]) : "r"(addr));
}
__device__ __forceinline__ void mma16816(float c[4], const uint32_t a[4],
                                         uint32_t b0, uint32_t b1) {
    asm volatile(
        "mma.sync.aligned.m16n8k16.row.col.f32.bf16.bf16.f32 "
        "{%0,%1,%2,%3},{%4,%5,%6,%7},{%8,%9},{%0,%1,%2,%3};"
        : "+f"(c[0]), "+f"(c[1]), "+f"(c[2]), "+f"(c[3])
        : "r"(a[0]), "r"(a[1]), "r"(a[2]), "r"(a[3]), "r"(b0), "r"(b1));
}
__device__ __forceinline__ void cp16(uint32_t dst, const void* src) {
    asm volatile("cp.async.ca.shared.global [%0], [%1], 16;"
        :: "r"(dst), "l"(src));
}
__device__ __forceinline__ void cp_commit() {
    asm volatile("cp.async.commit_group;");
}
template<int N>
__device__ __forceinline__ void cp_wait() {
    asm volatile("cp.async.wait_group %0;" :: "n"(N));
}
__device__ __forceinline__ bf16 tobf(float v) { return __float2bfloat16(v); }

// ============================================================================
// bf16x3 GEMM core: cp.async double-buffered, fragment reuse, all shared
// addresses precomputed in registers (stage toggle = one IADD per access).
// acc += Ah*Bh + Ah*Bl + Al*Bh.  Al = Ah + loA, Bl = Bh + loB.
// Block = 128 x BN, 256 threads (8 warps, wm=wid&3, wn=wid>>2).
// ============================================================================
template<int BN>
__device__ __forceinline__ void gemm_core(
    const bf16* __restrict__ Ah, long loA, int lda,
    const bf16* __restrict__ Bh, long loB, int ldb,
    int K, float acc[2][BN/16][4])
{
    constexpr int NT = BN / 16;
    constexpr int BSTR = BN + 40;            // 20 banks mod 32 -> conflict-free
    constexpr int ASZ = 2 * 128 * 40;        // elements per stage (hi+lo)
    constexpr int BSZ = 2 * 32 * BSTR;
    constexpr uint32_t ALOb = 128 * 40 * 2;  // hi->lo byte offset (within stage)
    constexpr uint32_t BLOb = 32 * BSTR * 2;
    constexpr uint32_t ASTb = ASZ * 2;       // stage byte stride
    constexpr uint32_t BSTb = BSZ * 2;
    __shared__ bf16 sA[2 * ASZ];
    __shared__ bf16 sB[2 * BSZ];
    const int tid = threadIdx.x;
    const int lane = tid & 31, wid = tid >> 5;
    const int wm = wid & 3, wn = wid >> 2;
    const int nTiles = K / 32;
    const uint32_t sAu = smem_u32(sA), sBu = smem_u32(sB);

    // ---- cp.async coordinates (precomputed) ----
    const int aR = tid >> 2, aC = (tid & 3) * 8;
    const int aR2 = aR + 64;                 // (tid+256)>>2
    const bf16* srcA0 = Ah + aR * lda + aC;
    const bf16* srcA1 = Ah + aR2 * lda + aC;
    const uint32_t dA0 = sAu + (uint32_t)(aR * 40 + aC) * 2;
    const uint32_t dA1 = sAu + (uint32_t)(aR2 * 40 + aC) * 2;
    constexpr int BCH = (BN / 8) * 32 / 256;
    const bf16* srcB[BCH];
    uint32_t dB[BCH];
#pragma unroll
    for (int i = 0; i < BCH; i++) {
        int id = tid + i * 256;
        int r = id / (BN / 8), cc = (id % (BN / 8)) * 8;
        srcB[i] = Bh + r * ldb + cc;
        dB[i] = sBu + (uint32_t)(r * BSTR + cc) * 2;
    }

    // ---- LDSM addresses (precomputed, stage 0) ----
    uint32_t bAddr[NT / 2];
#pragma unroll
    for (int np = 0; np < NT / 2; np++)
        bAddr[np] = sBu + (uint32_t)((lane & 15) * BSTR +
                     wn * (NT * 8) + np * 16 + ((lane >> 4) << 3)) * 2;
    uint32_t aAddr[2];
#pragma unroll
    for (int mt = 0; mt < 2; mt++)
        aAddr[mt] = sAu + (uint32_t)((wm * 32 + mt * 16 + (lane & 15)) * 40 +
                     ((lane >> 4) << 3)) * 2;

    auto loadTile = [&](uint32_t stA, uint32_t stB) {
        cp16(dA0 + stA, srcA0);  cp16(dA0 + ALOb + stA, srcA0 + loA);
        cp16(dA1 + stA, srcA1);  cp16(dA1 + ALOb + stA, srcA1 + loA);
        srcA0 += 32; srcA1 += 32;
#pragma unroll
        for (int i = 0; i < BCH; i++) {
            cp16(dB[i] + stB, srcB[i]);
            cp16(dB[i] + BLOb + stB, srcB[i] + loB);
            srcB[i] += 32 * ldb;
        }
    };

    loadTile(0, 0);
    cp_commit();

    for (int i = 0; i < nTiles; i++) {
        if (i + 1 < nTiles) {
            loadTile(((i + 1) & 1) ? ASTb : 0u, ((i + 1) & 1) ? BSTb : 0u);
            cp_commit();
            cp_wait<1>();
        } else {
            cp_wait<0>();
        }
        __syncthreads();

        const uint32_t stA = (i & 1) ? ASTb : 0u;
        const uint32_t stB = (i & 1) ? BSTb : 0u;
#pragma unroll
        for (int kk = 0; kk < 2; kk++) {
            const uint32_t kA = stA + (kk ? 32u : 0u);              // 16 el * 2B
            const uint32_t kB = stB + (kk ? 16u * BSTR * 2u : 0u);  // 16 rows
            uint32_t bh[NT][2];
#pragma unroll
            for (int np = 0; np < NT / 2; np++) {
                uint32_t rr[4];
                ldmBT(rr, bAddr[np] + kB);
                bh[2 * np][0] = rr[0]; bh[2 * np][1] = rr[1];
                bh[2 * np + 1][0] = rr[2]; bh[2 * np + 1][1] = rr[3];
            }
            uint32_t ah[2][4], al[2][4];
#pragma unroll
            for (int mt = 0; mt < 2; mt++) {
                ldmA(ah[mt], aAddr[mt] + kA);
                ldmA(al[mt], aAddr[mt] + ALOb + kA);
            }
#pragma unroll
            for (int mt = 0; mt < 2; mt++)
#pragma unroll
                for (int nt = 0; nt < NT; nt++) {
                    mma16816(acc[mt][nt], ah[mt], bh[nt][0], bh[nt][1]);
                    mma16816(acc[mt][nt], al[mt], bh[nt][0], bh[nt][1]);
                }
#pragma unroll
            for (int np = 0; np < NT / 2; np++) {
                uint32_t rr[4];
                ldmBT(rr, bAddr[np] + BLOb + kB);
#pragma unroll
                for (int mt = 0; mt < 2; mt++) {
                    mma16816(acc[mt][2 * np],     ah[mt], rr[0], rr[1]);
                    mma16816(acc[mt][2 * np + 1], ah[mt], rr[2], rr[3]);
                }
            }
        }
        __syncthreads();
    }
}

#define EPI_ROW(mt, r)     (wm * 32 + (mt) * 16 + (lane >> 2) + (((r) >> 1) << 3))
#define EPI_COL(nt, r, NT) (wn * ((NT) * 8) + (nt) * 8 + ((lane & 3) << 1) + ((r) & 1))

// ============================================================================
// split kernels: fp32 -> (bf16 hi, bf16 lo). blockIdx.y selects tensor.
// ============================================================================
__global__ void split_act_kernel(const float* __restrict__ q,
                                 const float* __restrict__ k,
                                 const float* __restrict__ v)
{
    const float* x; bf16 *h, *l;
    switch (blockIdx.y) {
        case 0:  x = q; h = g_q_h; l = g_q_l; break;
        case 1:  x = k; h = g_k_h; l = g_k_l; break;
        default: x = v; h = g_v_h; l = g_v_l; break;
    }
    int i = blockIdx.x * blockDim.x + threadIdx.x;
    float val = x[i];
    bf16 hv = tobf(val);
    h[i] = hv;
    l[i] = tobf(val - __bfloat162float(hv));
}

__global__ void split_w_kernel(const float* __restrict__ Wq,
                               const float* __restrict__ Wk,
                               const float* __restrict__ Wv,
                               const float* __restrict__ Wo)
{
    const float* x; bf16 *h, *l;
    switch (blockIdx.y) {
        case 0:  x = Wq; h = g_Wq_h; l = g_Wq_l; break;
        case 1:  x = Wk; h = g_Wk_h; l = g_Wk_l; break;
        case 2:  x = Wv; h = g_Wv_h; l = g_Wv_l; break;
        default: x = Wo; h = g_Wo_h; l = g_Wo_l; break;
    }
    int i = blockIdx.x * blockDim.x + threadIdx.x;
    float val = x[i];
    bf16 hv = tobf(val);
    h[i] = hv;
    l[i] = tobf(val - __bfloat162float(hv));
}

// ============================================================================
// Merged projection GEMM: blockIdx.z = which (0=Q,1=K,2=V).
// ============================================================================
__global__ __launch_bounds__(256, 2) void proj_mma_kernel()
{
    const int which = blockIdx.z;
    const bf16 *Ah, *Wh;
    long loA, loW;
    if (which == 0)      { Ah = g_q_h; loA = g_q_l - g_q_h; Wh = g_Wq_h; loW = g_Wq_l - g_Wq_h; }
    else if (which == 1) { Ah = g_k_h; loA = g_k_l - g_k_h; Wh = g_Wk_h; loW = g_Wk_l - g_Wk_h; }
    else                 { Ah = g_v_h; loA = g_v_l - g_v_h; Wh = g_Wv_h; loW = g_Wv_l - g_Wv_h; }
    const float scale = (which == 0) ? 0.125f : 1.0f;

    const int bm = blockIdx.y * 128, bn = blockIdx.x * 128;
    float acc[2][8][4];
#pragma unroll
    for (int i = 0; i < 2; i++)
#pragma unroll
        for (int j = 0; j < 8; j++)
#pragma unroll
            for (int r = 0; r < 4; r++) acc[i][j][r] = 0.f;

    gemm_core<128>(Ah + bm * 1024, loA, 1024, Wh + bn, loW, 1024, 1024, acc);

    const int lane = threadIdx.x & 31, wid = threadIdx.x >> 5;
    const int wm = wid & 3, wn = wid >> 2;
    bf16 *dh, *dl;
    if (which == 0)      { dh = g_qp_h;  dl = g_qp_l;  }
    else if (which == 1) { dh = g_kpT_h; dl = g_kpT_l; }
    else                 { dh = g_vp_h;  dl = g_vp_l;  }

    if (which == 1) {
#pragma unroll
        for (int mt = 0; mt < 2; mt++)
#pragma unroll
            for (int nt = 0; nt < 8; nt++)
#pragma unroll
                for (int r = 0; r < 4; r++) {
                    int row = bm + EPI_ROW(mt, r);
                    int col = bn + EPI_COL(nt, r, 8);
                    int t = row >> 3, b = row & 7;
                    int h = col >> 6, d = col & 63;
                    int n = b * 16 + h;
                    float v = acc[mt][nt][r];
                    int idx = (n * 64 + d) * 512 + t;
                    bf16 hv = tobf(v);
                    dh[idx] = hv;
                    dl[idx] = tobf(v - __bfloat162float(hv));
                }
    } else {
#pragma unroll
        for (int mt = 0; mt < 2; mt++)
#pragma unroll
            for (int nt = 0; nt < 8; nt++)
#pragma unroll
                for (int r2 = 0; r2 < 4; r2 += 2) {
                    int row = bm + EPI_ROW(mt, r2);
                    int col = bn + EPI_COL(nt, r2, 8);   // even
                    int t = row >> 3, b = row & 7;
                    int h = col >> 6, d = col & 63;
                    int n = b * 16 + h;
                    int idx = (n * 512 + t) * 64 + d;
                    float v0 = acc[mt][nt][r2] * scale;
                    float v1 = acc[mt][nt][r2 + 1] * scale;
                    bf16 h0 = tobf(v0), h1 = tobf(v1);
                    __nv_bfloat162 hp; hp.x = h0; hp.y = h1;
                    __nv_bfloat162 lp;
                    lp.x = tobf(v0 - __bfloat162float(h0));
                    lp.y = tobf(v1 - __bfloat162float(h1));
                    *(__nv_bfloat162*)&dh[idx] = hp;
                    *(__nv_bfloat162*)&dl[idx] = lp;
                }
    }
}

// ============================================================================
// Energy + sigmoid -> g_p (fp32)
// ============================================================================
__global__ __launch_bounds__(256, 2) void energy_mma_kernel(const float* __restrict__ ebias)
{
    const int n = blockIdx.z;
    const int t0 = blockIdx.y * 128, s0 = blockIdx.x * 128;
    float acc[2][8][4];
#pragma unroll
    for (int i = 0; i < 2; i++)
#pragma unroll
        for (int j = 0; j < 8; j++)
#pragma unroll
            for (int r = 0; r < 4; r++) acc[i][j][r] = 0.f;

    gemm_core<128>(g_qp_h + n * 512 * 64 + t0 * 64, g_qp_l - g_qp_h, 64,
                   g_kpT_h + n * 64 * 512 + s0,     g_kpT_l - g_kpT_h, 512,
                   64, acc);

    const int lane = threadIdx.x & 31, wid = threadIdx.x >> 5;
    const int wm = wid & 3, wn = wid >> 2;
    const float eb = ebias[0];
#pragma unroll
    for (int mt = 0; mt < 2; mt++)
#pragma unroll
        for (int nt = 0; nt < 8; nt++)
#pragma unroll
            for (int r2 = 0; r2 < 4; r2 += 2) {
                int t = t0 + EPI_ROW(mt, r2);
                int s = s0 + EPI_COL(nt, r2, 8);  // even
                float e0 = acc[mt][nt][r2] + eb;
                float e1 = acc[mt][nt][r2 + 1] + eb;
                float2 pv;
                pv.x = 1.f / (1.f + __expf(-e0));
                pv.y = 1.f / (1.f + __expf(-e1));
                *(float2*)&g_p[(n * 512 + t) * 512 + s] = pv;
            }
}

// ============================================================================
// Fused recurrence, 3 barriers/step.  Sum-scan(t) and cumprod-scan(t+1)
// interleaved (independent chains); warp0/warp1 do cross-warp prefixes
// concurrently.  One block per n (128), 512 threads (one per s).
// ============================================================================
__global__ __launch_bounds__(512) void recurrence_kernel()
{
    const int s = threadIdx.x;
    const int n = blockIdx.x;
    const int lane = s & 31, wid = s >> 5;
    const int base = n * 512 * 512 + s;

    __shared__ float sh_sw[16], sh_sp[16];
    __shared__ float sh_pw[16], sh_pp[16];
    __shared__ float sh_m[16];

    // ---- prologue: exclusive cumprod for t=0 ----
    float p = g_p[base];
    float cl, pc;
    {
        float v = 1.f - p;
#pragma unroll
        for (int o = 1; o < 32; o <<= 1) {
            float u = __shfl_up_sync(0xffffffffu, v, o);
            if (lane >= o) v *= u;
        }
        if (lane == 31) sh_pw[wid] = v;
        __syncthreads();
        if (wid == 0) {
            float w = (lane < 16) ? sh_pw[lane] : 1.f;
#pragma unroll
            for (int o = 1; o < 16; o <<= 1) {
                float u = __shfl_up_sync(0xffffffffu, w, o);
                if (lane >= o) w *= u;
            }
            if (lane < 16) sh_pp[lane] = w;
        }
        __syncthreads();
        float woff = (wid > 0) ? sh_pp[wid - 1] : 1.f;
        float inclp = v * woff;
        float cp = __shfl_up_sync(0xffffffffu, inclp, 1);
        if (lane == 0) cp = woff;
        if (s == 0) cp = 1.f;
        cl = fminf(fmaxf(cp, 1e-6f), 1.f);
        pc = p * cp;
    }
    float aprev = (s == 0) ? 1.f : 0.f;

    for (int t = 0; t < 512; t++) {
        float pnext = (t < 511) ? g_p[base + (t + 1) * 512] : 0.f;

        // interleaved scans: sum of aprev/cl (row t), product of 1-pnext (t+1)
        float u2 = aprev / cl;
        float vb = 1.f - pnext;
#pragma unroll
        for (int o = 1; o < 32; o <<= 1) {
            float uu = __shfl_up_sync(0xffffffffu, u2, o);
            float vv = __shfl_up_sync(0xffffffffu, vb, o);
            if (lane >= o) { u2 += uu; vb *= vv; }
        }
        if (lane == 31) { sh_sw[wid] = u2; sh_pw[wid] = vb; }
        __syncthreads();
        if (wid == 0) {
            float w = (lane < 16) ? sh_sw[lane] : 0.f;
#pragma unroll
            for (int o = 1; o < 16; o <<= 1) {
                float uu = __shfl_up_sync(0xffffffffu, w, o);
                if (lane >= o) w += uu;
            }
            if (lane < 16) sh_sp[lane] = w;
        } else if (wid == 1) {
            float w = (lane < 16) ? sh_pw[lane] : 1.f;
#pragma unroll
            for (int o = 1; o < 16; o <<= 1) {
                float uu = __shfl_up_sync(0xffffffffu, w, o);
                if (lane >= o) w *= uu;
            }
            if (lane < 16) sh_pp[lane] = w;
        }
        __syncthreads();

        float incl2 = u2 + ((wid > 0) ? sh_sp[wid - 1] : 0.f);
        float araw = fminf(fmaxf(pc * incl2, 0.f), 1.f);

        // next-row cumprod finish
        float woff = (wid > 0) ? sh_pp[wid - 1] : 1.f;
        float inclp = vb * woff;
        float cpn = __shfl_up_sync(0xffffffffu, inclp, 1);
        if (lane == 0) cpn = woff;
        if (s == 0) cpn = 1.f;
        float cln = fminf(fmaxf(cpn, 1e-6f), 1.f);
        float pcn = pnext * cpn;

        // store non-last columns now
        if (s < 511) {
            bf16 hv = tobf(araw);
            g_al_h[base + t * 512] = hv;
            g_al_l[base + t * 512] = tobf(araw - __bfloat162float(hv));
        }

        // mass reduction (sum over s<511)
        float yv = (s < 511) ? araw : 0.f;
#pragma unroll
        for (int o = 16; o > 0; o >>= 1)
            yv += __shfl_xor_sync(0xffffffffu, yv, o);
        if (lane == 0) sh_m[wid] = yv;
        __syncthreads();

        if (s == 511) {
            float total = 0.f;
#pragma unroll
            for (int i = 0; i < 16; i++) total += sh_m[i];
            float aout = 1.f - fminf(fmaxf(total, 0.f), 1.f);
            bf16 hv = tobf(aout);
            g_al_h[base + t * 512] = hv;
            g_al_l[base + t * 512] = tobf(aout - __bfloat162float(hv));
        }

        aprev = araw;
        cl = cln;
        pc = pcn;
    }
}

// ============================================================================
// attn = alpha @ vp  (per n: [512x512]@[512x64]) -> merged hi/lo.
// ============================================================================
__global__ __launch_bounds__(256, 2) void attnv_mma_kernel()
{
    const int n = blockIdx.z;
    const int t0 = blockIdx.y * 128;
    float acc[2][4][4];
#pragma unroll
    for (int i = 0; i < 2; i++)
#pragma unroll
        for (int j = 0; j < 4; j++)
#pragma unroll
            for (int r = 0; r < 4; r++) acc[i][j][r] = 0.f;

    gemm_core<64>(g_al_h + n * 512 * 512 + t0 * 512, g_al_l - g_al_h, 512,
                  g_vp_h + n * 512 * 64,             g_vp_l - g_vp_h, 64,
                  512, acc);

    const int lane = threadIdx.x & 31, wid = threadIdx.x >> 5;
    const int wm = wid & 3, wn = wid >> 2;
    const int b = n >> 4, h = n & 15;
#pragma unroll
    for (int mt = 0; mt < 2; mt++)
#pragma unroll
        for (int nt = 0; nt < 4; nt++)
#pragma unroll
            for (int r2 = 0; r2 < 4; r2 += 2) {
                int t = t0 + EPI_ROW(mt, r2);
                int d = EPI_COL(nt, r2, 4);   // even
                int idx = (t * 8 + b) * 1024 + h * 64 + d;
                float v0 = acc[mt][nt][r2], v1 = acc[mt][nt][r2 + 1];
                bf16 h0 = tobf(v0), h1 = tobf(v1);
                __nv_bfloat162 hp; hp.x = h0; hp.y = h1;
                __nv_bfloat162 lp;
                lp.x = tobf(v0 - __bfloat162float(h0));
                lp.y = tobf(v1 - __bfloat162float(h1));
                *(__nv_bfloat162*)&g_at_h[idx] = hp;
                *(__nv_bfloat162*)&g_at_l[idx] = lp;
            }
}

// ============================================================================
// Output projection: out = attn[4096x1024] @ Wo + bo (fp32 out)
// ============================================================================
__global__ __launch_bounds__(256, 2) void out_mma_kernel(
    const float* __restrict__ bias, float* __restrict__ out)
{
    const int bm = blockIdx.y * 128, bn = blockIdx.x * 128;
    float acc[2][8][4];
#pragma unroll
    for (int i = 0; i < 2; i++)
#pragma unroll
        for (int j = 0; j < 8; j++)
#pragma unroll
            for (int r = 0; r < 4; r++) acc[i][j][r] = 0.f;

    gemm_core<128>(g_at_h + bm * 1024, g_at_l - g_at_h, 1024,
                   g_Wo_h + bn,        g_Wo_l - g_Wo_h, 1024, 1024, acc);

    const int lane = threadIdx.x & 31, wid = threadIdx.x >> 5;
    const int wm = wid & 3, wn = wid >> 2;
#pragma unroll
    for (int mt = 0; mt < 2; mt++)
#pragma unroll
        for (int nt = 0; nt < 8; nt++)
#pragma unroll
            for (int r2 = 0; r2 < 4; r2 += 2) {
                int row = bm + EPI_ROW(mt, r2);
                int col = bn + EPI_COL(nt, r2, 8);  // even
                float2 ov;
                ov.x = acc[mt][nt][r2]     + bias[col];
                ov.y = acc[mt][nt][r2 + 1] + bias[col + 1];
                *(float2*)&out[row * 1024 + col] = ov;
            }
}

// ============================================================================
extern "C" void kernel_launch(void* const* d_in, const int* in_sizes, int n_in,
                              void* d_out, int out_size)
{
    const float* q  = (const float*)d_in[0];
    const float* k  = (const float*)d_in[1];
    const float* v  = (const float*)d_in[2];
    const float* Wq = (const float*)d_in[3];
    const float* Wk = (const float*)d_in[4];
    const float* Wv = (const float*)d_in[5];
    const float* Wo = (const float*)d_in[6];
    const float* bo = (const float*)d_in[7];
    const float* eb = (const float*)d_in[8];
    float* out = (float*)d_out;

    split_act_kernel<<<dim3(MROWS * EMBED / 256, 3), 256>>>(q, k, v);
    split_w_kernel<<<dim3(EMBED * EMBED / 256, 4), 256>>>(Wq, Wk, Wv, Wo);

    proj_mma_kernel<<<dim3(8, 32, 3), 256>>>();
    energy_mma_kernel<<<dim3(4, 4, 128), 256>>>(eb);
    recurrence_kernel<<<128, 512>>>();
    attnv_mma_kernel<<<dim3(1, 4, 128), 256>>>();
    out_mma_kernel<<<dim3(8, 32), 256>>>(bo, out);
}